// round 7
// baseline (speedup 1.0000x reference)
#include <cuda_runtime.h>
#include <cuda_fp16.h>
#include <cstdint>

#define NFINE   1000000
#define NCOARSE 250000
#define FE      9
#define NF      64
#define BLOCK_M 128
#define THREADS 512              // 16 warps: (wid&7)=m-tile(m16), (wid>>3)=n-half(n32)
#define WSTRIDE 72               // B half2-row stride (u32 words): bank=(8qc+qr)%32 bijective
#define ASTRIDE 20               // A row stride (u32 words): 64B data + 16B pad,
                                 // bank=(20qr+qc)%32 bijective -> conflict-free

// smem layout (u32 units)
#define WS_U32   (144 * WSTRIDE)           // 10368 (288 halves = 144 half2 rows)
#define A_OFF    WS_U32
#define A_U32    (BLOCK_M * ASTRIDE)       // 2560 per slab buffer
#define IDX_OFF  (A_OFF + 2 * A_U32)       // 15488
#define IDX_U32  (BLOCK_M * FE)            // 1152 per idx buffer
#define SMEM_U32 (IDX_OFF + 2 * IDX_U32)   // 17792
#define SMEM_BYTES (SMEM_U32 * 4)          // 71168 B -> 2 CTAs/SM

// fp16 copy of coarse values (filled by conv_coarse pre-pass each launch)
__device__ __half g_ch[NCOARSE * 32];      // 16 MB

__global__ void __launch_bounds__(256)
conv_coarse(const float4* __restrict__ src)
{
    uint2* dst = (uint2*)g_ch;
    const int n4 = NCOARSE * 8;            // 2,000,000 float4s
    for (int i = blockIdx.x * blockDim.x + threadIdx.x; i < n4;
         i += gridDim.x * blockDim.x) {
        float4 v = src[i];
        __half2 h0 = __floats2half2_rn(v.x, v.y);
        __half2 h1 = __floats2half2_rn(v.z, v.w);
        dst[i] = make_uint2(*(uint32_t*)&h0, *(uint32_t*)&h1);
    }
}

__device__ __forceinline__ void cp_commit() { asm volatile("cp.async.commit_group;"); }
template<int N> __device__ __forceinline__ void cp_wait() {
    asm volatile("cp.async.wait_group %0;" :: "n"(N));
}

// Gather one neighbor slab j: 128 rows x 64B, 1 cp.async(16B) per thread.
__device__ __forceinline__ void gather_slab(const int* __restrict__ sidx, int j,
                                            uint32_t abuf)
{
    int r   = threadIdx.x >> 2;
    int seg = threadIdx.x & 3;
    int idx = sidx[r * FE + j];
    const char* src = (const char*)g_ch + ((size_t)(unsigned)idx << 6) + (seg << 4);
    uint32_t dst = abuf + (uint32_t)r * (ASTRIDE * 4) + (uint32_t)(seg << 4);
    asm volatile("cp.async.cg.shared.global [%0], [%1], 16;" :: "r"(dst), "l"(src));
}

// Stage 128x9 neighbor indices for one tile (tail: clamp; stale rows stay valid).
__device__ __forceinline__ void stage_idx(const int* __restrict__ nbr, int tile,
                                          uint32_t dst)
{
    const size_t base = (size_t)tile * (BLOCK_M * FE);
    if (base + BLOCK_M * FE <= (size_t)NFINE * FE) {
        if (threadIdx.x < BLOCK_M * FE / 4)
            asm volatile("cp.async.ca.shared.global [%0], [%1], 16;"
                         :: "r"(dst + threadIdx.x * 16), "l"(nbr + base + threadIdx.x * 4));
    } else {
        const size_t gmax = (size_t)NFINE * FE - 1;
        for (int i = threadIdx.x; i < BLOCK_M * FE; i += THREADS) {
            size_t g = base + i; if (g > gmax) g = gmax;
            asm volatile("cp.async.ca.shared.global [%0], [%1], 4;"
                         :: "r"(dst + i * 4), "l"(nbr + g));
        }
    }
}

__global__ void __launch_bounds__(THREADS, 2)
finefy_fp16_kernel(const int*   __restrict__ nbr,
                   const float* __restrict__ weight,
                   float*       __restrict__ out,
                   int numTiles)
{
    extern __shared__ uint32_t sm_[];
    uint32_t* ws = sm_;
    const uint32_t sb = (uint32_t)__cvta_generic_to_shared(sm_);

    const int tid  = threadIdx.x;
    const int lane = tid & 31;
    const int wid  = tid >> 5;
    const int qr   = lane >> 2;      // 0..7
    const int qc   = lane & 3;       // 0..3
    const int mw   = wid & 7;        // m-tile (rows mw*16..+15)
    const int nh   = wid >> 3;       // n-half (cols nh*32..+31)

    // Weight -> fp16, packed as half2 along K: B half index = (r*WSTRIDE+n)*2 + (k&1)
    for (int i = tid; i < 288 * NF; i += THREADS) {
        int k = i >> 6, n = i & 63;
        ((__half*)ws)[((k >> 1) * WSTRIDE + n) * 2 + (k & 1)] = __float2half_rn(weight[i]);
    }

    const int step = gridDim.x;
    int tile = blockIdx.x;
    int ibuf = 0;   // idx buffer for current tile
    int sbuf = 0;   // slab buffer about to be computed

    if (tile < numTiles) {
        stage_idx(nbr, tile, sb + IDX_OFF * 4);
        cp_commit(); cp_wait<0>(); __syncthreads();
        gather_slab((const int*)(sm_ + IDX_OFF), 0, sb + A_OFF * 4);
        cp_commit();
    }

    for (; tile < numTiles; tile += step) {
        const int* sidx = (const int*)(sm_ + IDX_OFF + ibuf * IDX_U32);

        float acc[4][4];
        #pragma unroll
        for (int i = 0; i < 4; ++i) {
            acc[i][0] = 0.f; acc[i][1] = 0.f; acc[i][2] = 0.f; acc[i][3] = 0.f;
        }

        for (int j = 0; j < FE; ++j) {
            if (j < FE - 1) {
                gather_slab(sidx, j + 1, sb + (A_OFF + (sbuf ^ 1) * A_U32) * 4);
                if (j == FE - 2 && tile + step < numTiles)
                    stage_idx(nbr, tile + step, sb + (IDX_OFF + (ibuf ^ 1) * IDX_U32) * 4);
                cp_commit();
                cp_wait<1>();            // slab j landed; j+1 in flight
            } else {
                cp_wait<0>();            // last slab (+ next idx) landed
            }
            __syncthreads();

            const uint32_t* ar = sm_ + A_OFF + sbuf * A_U32 + (mw * 16 + qr) * ASTRIDE + qc;

            #pragma unroll
            for (int kk = 0; kk < 2; ++kk) {     // two k16 steps cover 32 dims
                const int c = kk * 8;
                uint32_t a0 = ar[c];
                uint32_t a2 = ar[c + 4];
                uint32_t a1 = ar[c     + 8 * ASTRIDE];
                uint32_t a3 = ar[c + 4 + 8 * ASTRIDE];

                const uint32_t* wrow = ws + (j * 16 + kk * 8 + qc) * WSTRIDE + nh * 32 + qr;

                #pragma unroll
                for (int t = 0; t < 4; ++t) {
                    uint32_t b0 = wrow[t * 8];
                    uint32_t b1 = wrow[t * 8 + 4 * WSTRIDE];
                    asm volatile(
                        "mma.sync.aligned.m16n8k16.row.col.f32.f16.f16.f32 "
                        "{%0,%1,%2,%3}, {%4,%5,%6,%7}, {%8,%9}, {%0,%1,%2,%3};"
                        : "+f"(acc[t][0]), "+f"(acc[t][1]),
                          "+f"(acc[t][2]), "+f"(acc[t][3])
                        : "r"(a0), "r"(a1), "r"(a2), "r"(a3), "r"(b0), "r"(b1));
                }
            }
            __syncthreads();             // all warps done with slab j before overwrite
            sbuf ^= 1;
        }

        // Prefetch next tile's slab 0 so its latency hides under the epilogue.
        if (tile + step < numTiles) {
            gather_slab((const int*)(sm_ + IDX_OFF + (ibuf ^ 1) * IDX_U32), 0,
                        sb + (A_OFF + sbuf * A_U32) * 4);
            cp_commit();
        }

        // Epilogue: coalesced streaming float2 stores.
        const int rowbase = tile * BLOCK_M;
        #pragma unroll
        for (int h = 0; h < 2; ++h) {
            int r = rowbase + mw * 16 + h * 8 + qr;
            if (r < NFINE) {
                float2* po = (float2*)(out + (size_t)r * NF + nh * 32 + qc * 2);
                #pragma unroll
                for (int t = 0; t < 4; ++t)
                    __stcs(po + t * 4, make_float2(acc[t][2*h], acc[t][2*h + 1]));
            }
        }
        ibuf ^= 1;
    }
}

extern "C" void kernel_launch(void* const* d_in, const int* in_sizes, int n_in,
                              void* d_out, int out_size)
{
    const float* coarse = (const float*)d_in[0];   // [250000, 32] f32
    const int*   nbr    = (const int*)  d_in[1];   // [1000000, 9] i32
    const float* weight = (const float*)d_in[2];   // [288, 64] f32
    float*       out    = (float*)d_out;           // [1000000, 64] f32

    cudaFuncSetAttribute(finefy_fp16_kernel,
                         cudaFuncAttributeMaxDynamicSharedMemorySize, SMEM_BYTES);

    int nsm = 148;
    cudaDeviceGetAttribute(&nsm, cudaDevAttrMultiProcessorCount, 0);

    // Pre-pass: convert coarse lattice to fp16 (deterministic, graph-capturable).
    conv_coarse<<<nsm * 4, 256>>>((const float4*)coarse);

    const int numTiles = (NFINE + BLOCK_M - 1) / BLOCK_M;   // 7813
    finefy_fp16_kernel<<<nsm * 2, THREADS, SMEM_BYTES>>>(nbr, weight, out, numTiles);
}

// round 8
// speedup vs baseline: 1.0077x; 1.0077x over previous
#include <cuda_runtime.h>
#include <cuda_fp16.h>
#include <cstdint>

#define NFINE   1000000
#define NCOARSE 250000
#define FE      9
#define NF      64
#define BLOCK_M 128
#define THREADS 512              // 16 warps: (wid&3)=m-tile(m32), (wid>>2)=n-quarter(n16)
#define WSTRIDE 72               // B half2-row stride (u32 words)
#define ASTRIDE 20               // A row stride (u32 words): 64B data + 16B pad,
                                 // bank=(20qr+qc)%32 bijective -> conflict-free

// smem layout (u32 units)
#define WS_U32   (144 * WSTRIDE)           // 10368 (288 halves = 144 half2 rows)
#define A_OFF    WS_U32
#define A_U32    (BLOCK_M * ASTRIDE)       // 2560 per slab buffer
#define IDX_OFF  (A_OFF + 2 * A_U32)       // 15488
#define IDX_U32  (BLOCK_M * FE)            // 1152 per idx buffer
#define SMEM_U32 (IDX_OFF + 2 * IDX_U32)   // 17792
#define SMEM_BYTES (SMEM_U32 * 4)          // 71168 B

// fp16 copy of coarse values (filled by conv_coarse pre-pass each launch)
__device__ __half g_ch[NCOARSE * 32];      // 16 MB

__global__ void __launch_bounds__(256)
conv_coarse(const float4* __restrict__ src)
{
    uint2* dst = (uint2*)g_ch;
    const int n4 = NCOARSE * 8;
    for (int i = blockIdx.x * blockDim.x + threadIdx.x; i < n4;
         i += gridDim.x * blockDim.x) {
        float4 v = src[i];
        __half2 h0 = __floats2half2_rn(v.x, v.y);
        __half2 h1 = __floats2half2_rn(v.z, v.w);
        dst[i] = make_uint2(*(uint32_t*)&h0, *(uint32_t*)&h1);
    }
}

__device__ __forceinline__ void cp_commit() { asm volatile("cp.async.commit_group;"); }
template<int N> __device__ __forceinline__ void cp_wait() {
    asm volatile("cp.async.wait_group %0;" :: "n"(N));
}

// Gather one neighbor slab j: 128 rows x 64B, 1 cp.async(16B) per thread.
__device__ __forceinline__ void gather_slab(const int* __restrict__ sidx, int j,
                                            uint32_t abuf)
{
    int r   = threadIdx.x >> 2;
    int seg = threadIdx.x & 3;
    int idx = sidx[r * FE + j];
    const char* src = (const char*)g_ch + ((size_t)(unsigned)idx << 6) + (seg << 4);
    uint32_t dst = abuf + (uint32_t)r * (ASTRIDE * 4) + (uint32_t)(seg << 4);
    asm volatile("cp.async.cg.shared.global [%0], [%1], 16;" :: "r"(dst), "l"(src));
}

// Stage 128x9 neighbor indices for one tile (tail: clamp; stale rows stay valid).
__device__ __forceinline__ void stage_idx(const int* __restrict__ nbr, int tile,
                                          uint32_t dst)
{
    const size_t base = (size_t)tile * (BLOCK_M * FE);
    if (base + BLOCK_M * FE <= (size_t)NFINE * FE) {
        if (threadIdx.x < BLOCK_M * FE / 4)
            asm volatile("cp.async.ca.shared.global [%0], [%1], 16;"
                         :: "r"(dst + threadIdx.x * 16), "l"(nbr + base + threadIdx.x * 4));
    } else {
        const size_t gmax = (size_t)NFINE * FE - 1;
        for (int i = threadIdx.x; i < BLOCK_M * FE; i += THREADS) {
            size_t g = base + i; if (g > gmax) g = gmax;
            asm volatile("cp.async.ca.shared.global [%0], [%1], 4;"
                         :: "r"(dst + i * 4), "l"(nbr + g));
        }
    }
}

__global__ void __launch_bounds__(THREADS, 1)
finefy_fp16_kernel(const int*   __restrict__ nbr,
                   const float* __restrict__ weight,
                   float*       __restrict__ out,
                   int numTiles)
{
    extern __shared__ uint32_t sm_[];
    uint32_t* ws = sm_;
    const uint32_t sb = (uint32_t)__cvta_generic_to_shared(sm_);

    const int tid  = threadIdx.x;
    const int lane = tid & 31;
    const int wid  = tid >> 5;
    const int qr   = lane >> 2;      // 0..7
    const int qc   = lane & 3;       // 0..3
    const int mw   = wid & 3;        // m-tile (rows mw*32..+31)
    const int nh   = wid >> 2;       // n-quarter (cols nh*16..+15)

    // Weight -> fp16, packed as half2 along K: B half index = (r*WSTRIDE+n)*2 + (k&1)
    for (int i = tid; i < 288 * NF; i += THREADS) {
        int k = i >> 6, n = i & 63;
        ((__half*)ws)[((k >> 1) * WSTRIDE + n) * 2 + (k & 1)] = __float2half_rn(weight[i]);
    }
    __syncthreads();

    // Register-persistent B: 18 k16-steps x (2 n8-tiles x {b0,b1}) = 72 regs.
    uint32_t bB[72];
    #pragma unroll
    for (int s = 0; s < 18; ++s) {
        #pragma unroll
        for (int t = 0; t < 2; ++t) {
            const uint32_t* w0 = ws + (s * 8 + qc) * WSTRIDE + nh * 16 + t * 8 + qr;
            bB[s * 4 + t * 2]     = w0[0];
            bB[s * 4 + t * 2 + 1] = w0[4 * WSTRIDE];
        }
    }

    const int step = gridDim.x;
    int tile = blockIdx.x;
    int ibuf = 0;   // idx buffer for current tile
    int sbuf = 0;   // slab buffer about to be computed

    if (tile < numTiles) {
        stage_idx(nbr, tile, sb + IDX_OFF * 4);
        cp_commit(); cp_wait<0>(); __syncthreads();
        gather_slab((const int*)(sm_ + IDX_OFF), 0, sb + A_OFF * 4);
        cp_commit();
    }

    for (; tile < numTiles; tile += step) {
        const int* sidx = (const int*)(sm_ + IDX_OFF + ibuf * IDX_U32);

        float acc[2][2][4];   // [m16-half][n8-tile][frag]
        #pragma unroll
        for (int i = 0; i < 2; ++i)
            #pragma unroll
            for (int t = 0; t < 2; ++t) {
                acc[i][t][0] = 0.f; acc[i][t][1] = 0.f;
                acc[i][t][2] = 0.f; acc[i][t][3] = 0.f;
            }

        #pragma unroll
        for (int j = 0; j < FE; ++j) {
            if (j < FE - 1) {
                gather_slab(sidx, j + 1, sb + (A_OFF + (sbuf ^ 1) * A_U32) * 4);
                if (j == FE - 2 && tile + step < numTiles)
                    stage_idx(nbr, tile + step, sb + (IDX_OFF + (ibuf ^ 1) * IDX_U32) * 4);
                cp_commit();
                cp_wait<1>();            // slab j landed; j+1 in flight
            } else {
                cp_wait<0>();            // last slab (+ next idx) landed
            }
            __syncthreads();

            const uint32_t* ar0 = sm_ + A_OFF + sbuf * A_U32 + (mw * 32 + qr) * ASTRIDE + qc;

            #pragma unroll
            for (int s2 = 0; s2 < 2; ++s2) {        // two m16 halves of m32
                const uint32_t* ar = ar0 + s2 * 16 * ASTRIDE;
                #pragma unroll
                for (int kk = 0; kk < 2; ++kk) {     // two k16 steps cover 32 dims
                    const int c = kk * 8;
                    uint32_t a0 = ar[c];
                    uint32_t a2 = ar[c + 4];
                    uint32_t a1 = ar[c     + 8 * ASTRIDE];
                    uint32_t a3 = ar[c + 4 + 8 * ASTRIDE];

                    const int s = j * 2 + kk;        // static after unroll
                    #pragma unroll
                    for (int t = 0; t < 2; ++t) {
                        asm volatile(
                            "mma.sync.aligned.m16n8k16.row.col.f32.f16.f16.f32 "
                            "{%0,%1,%2,%3}, {%4,%5,%6,%7}, {%8,%9}, {%0,%1,%2,%3};"
                            : "+f"(acc[s2][t][0]), "+f"(acc[s2][t][1]),
                              "+f"(acc[s2][t][2]), "+f"(acc[s2][t][3])
                            : "r"(a0), "r"(a1), "r"(a2), "r"(a3),
                              "r"(bB[s * 4 + t * 2]), "r"(bB[s * 4 + t * 2 + 1]));
                    }
                }
            }
            __syncthreads();             // all warps done with slab j before overwrite
            sbuf ^= 1;
        }

        // Prefetch next tile's slab 0 so its latency hides under the epilogue.
        if (tile + step < numTiles) {
            gather_slab((const int*)(sm_ + IDX_OFF + (ibuf ^ 1) * IDX_U32), 0,
                        sb + (A_OFF + sbuf * A_U32) * 4);
            cp_commit();
        }

        // Epilogue: coalesced streaming float2 stores.
        const int rowbase = tile * BLOCK_M;
        #pragma unroll
        for (int s2 = 0; s2 < 2; ++s2) {
            #pragma unroll
            for (int h = 0; h < 2; ++h) {
                int r = rowbase + mw * 32 + s2 * 16 + h * 8 + qr;
                if (r < NFINE) {
                    float2* po = (float2*)(out + (size_t)r * NF + nh * 16 + qc * 2);
                    #pragma unroll
                    for (int t = 0; t < 2; ++t)
                        __stcs(po + t * 4,
                               make_float2(acc[s2][t][2*h], acc[s2][t][2*h + 1]));
                }
            }
        }
        ibuf ^= 1;
    }
}

extern "C" void kernel_launch(void* const* d_in, const int* in_sizes, int n_in,
                              void* d_out, int out_size)
{
    const float* coarse = (const float*)d_in[0];   // [250000, 32] f32
    const int*   nbr    = (const int*)  d_in[1];   // [1000000, 9] i32
    const float* weight = (const float*)d_in[2];   // [288, 64] f32
    float*       out    = (float*)d_out;           // [1000000, 64] f32

    cudaFuncSetAttribute(finefy_fp16_kernel,
                         cudaFuncAttributeMaxDynamicSharedMemorySize, SMEM_BYTES);

    int nsm = 148;
    cudaDeviceGetAttribute(&nsm, cudaDevAttrMultiProcessorCount, 0);

    // Pre-pass: convert coarse lattice to fp16 (deterministic, graph-capturable).
    conv_coarse<<<nsm * 4, 256>>>((const float4*)coarse);

    const int numTiles = (NFINE + BLOCK_M - 1) / BLOCK_M;   // 7813
    finefy_fp16_kernel<<<nsm, THREADS, SMEM_BYTES>>>(nbr, weight, out, numTiles);
}

// round 9
// speedup vs baseline: 1.0729x; 1.0647x over previous
#include <cuda_runtime.h>
#include <cuda_fp16.h>
#include <cstdint>

#define NFINE   1000000
#define NCOARSE 250000
#define FE      9
#define NF      64
#define BLOCK_M 128
#define THREADS 512              // 16 warps: (wid&7)=m-tile(m16), (wid>>3)=n-half(n32)
#define WSTRIDE 72               // B half2-row stride (u32 words): conflict-free B LDS
#define ASTRIDE 20               // A row stride (u32 words): 64B data + 16B pad,
                                 // bank=(20qr+qc)%32 bijective -> conflict-free

// smem layout (u32 units)
#define WS_U32   (144 * WSTRIDE)           // 10368
#define A_OFF    WS_U32                    // 4 slab buffers (pipeline depth 4)
#define A_U32    (BLOCK_M * ASTRIDE)       // 2560 per slab buffer
#define IDX_OFF  (A_OFF + 4 * A_U32)       // 20608
#define IDX_U32  (BLOCK_M * FE)            // 1152 per idx buffer
#define SMEM_U32 (IDX_OFF + 2 * IDX_U32)   // 22912
#define SMEM_BYTES (SMEM_U32 * 4)          // 91648 B -> 2 CTAs/SM

// fp16 copy of coarse values (filled by conv_coarse pre-pass each launch)
__device__ __half g_ch[NCOARSE * 32];      // 16 MB

__global__ void __launch_bounds__(256)
conv_coarse(const float4* __restrict__ src)
{
    uint2* dst = (uint2*)g_ch;
    const int n4 = NCOARSE * 8;
    for (int i = blockIdx.x * blockDim.x + threadIdx.x; i < n4;
         i += gridDim.x * blockDim.x) {
        float4 v = src[i];
        __half2 h0 = __floats2half2_rn(v.x, v.y);
        __half2 h1 = __floats2half2_rn(v.z, v.w);
        dst[i] = make_uint2(*(uint32_t*)&h0, *(uint32_t*)&h1);
    }
}

__device__ __forceinline__ void cp_commit() { asm volatile("cp.async.commit_group;"); }
template<int N> __device__ __forceinline__ void cp_wait() {
    asm volatile("cp.async.wait_group %0;" :: "n"(N));
}

// Gather one neighbor slab j: 128 rows x 64B, 1 cp.async(16B) per thread.
__device__ __forceinline__ void gather_slab(const int* __restrict__ sidx, int j,
                                            uint32_t abuf)
{
    int r   = threadIdx.x >> 2;
    int seg = threadIdx.x & 3;
    int idx = sidx[r * FE + j];
    const char* src = (const char*)g_ch + ((size_t)(unsigned)idx << 6) + (seg << 4);
    uint32_t dst = abuf + (uint32_t)r * (ASTRIDE * 4) + (uint32_t)(seg << 4);
    asm volatile("cp.async.cg.shared.global [%0], [%1], 16;" :: "r"(dst), "l"(src));
}

// Stage 128x9 neighbor indices for one tile (tail: clamp; stale rows stay valid).
__device__ __forceinline__ void stage_idx(const int* __restrict__ nbr, int tile,
                                          uint32_t dst)
{
    const size_t base = (size_t)tile * (BLOCK_M * FE);
    if (base + BLOCK_M * FE <= (size_t)NFINE * FE) {
        if (threadIdx.x < BLOCK_M * FE / 4)
            asm volatile("cp.async.ca.shared.global [%0], [%1], 16;"
                         :: "r"(dst + threadIdx.x * 16), "l"(nbr + base + threadIdx.x * 4));
    } else {
        const size_t gmax = (size_t)NFINE * FE - 1;
        for (int i = threadIdx.x; i < BLOCK_M * FE; i += THREADS) {
            size_t g = base + i; if (g > gmax) g = gmax;
            asm volatile("cp.async.ca.shared.global [%0], [%1], 4;"
                         :: "r"(dst + i * 4), "l"(nbr + g));
        }
    }
}

__global__ void __launch_bounds__(THREADS, 2)
finefy_fp16_kernel(const int*   __restrict__ nbr,
                   const float* __restrict__ weight,
                   float*       __restrict__ out,
                   int numTiles)
{
    extern __shared__ uint32_t sm_[];
    uint32_t* ws = sm_;
    const uint32_t sb = (uint32_t)__cvta_generic_to_shared(sm_);

    const int tid  = threadIdx.x;
    const int lane = tid & 31;
    const int wid  = tid >> 5;
    const int qr   = lane >> 2;      // 0..7
    const int qc   = lane & 3;       // 0..3
    const int mw   = wid & 7;        // m-tile (rows mw*16..+15)
    const int nh   = wid >> 3;       // n-half (cols nh*32..+31)

    // Weight -> fp16, packed as half2 along K: B half index = (r*WSTRIDE+n)*2 + (k&1)
    for (int i = tid; i < 288 * NF; i += THREADS) {
        int k = i >> 6, n = i & 63;
        ((__half*)ws)[((k >> 1) * WSTRIDE + n) * 2 + (k & 1)] = __float2half_rn(weight[i]);
    }

    const int step = gridDim.x;
    int tile = blockIdx.x;
    int ibuf = 0;       // idx buffer holding current tile's indices
    int cons = 0;       // slab buffer about to be consumed (cycles mod 4)

    // ---- Prologue: stage idx for first tile, then fill the 4-deep slab pipe ----
    if (tile < numTiles) {
        stage_idx(nbr, tile, sb + IDX_OFF * 4);
        cp_commit(); cp_wait<0>(); __syncthreads();
        const int* sidx0 = (const int*)(sm_ + IDX_OFF);
        #pragma unroll
        for (int p = 0; p < 4; ++p) {
            gather_slab(sidx0, p, sb + (A_OFF + p * A_U32) * 4);
            cp_commit();
        }
    }

    for (; tile < numTiles; tile += step) {
        const int* sidx  = (const int*)(sm_ + IDX_OFF + ibuf * IDX_U32);
        const int* nsidx = (const int*)(sm_ + IDX_OFF + (ibuf ^ 1) * IDX_U32);
        const bool has_next = (tile + step) < numTiles;

        float acc[4][4];
        #pragma unroll
        for (int i = 0; i < 4; ++i) {
            acc[i][0] = 0.f; acc[i][1] = 0.f; acc[i][2] = 0.f; acc[i][3] = 0.f;
        }

        #pragma unroll
        for (int j = 0; j < FE; ++j) {
            cp_wait<3>();                // slab j (oldest of 4 groups) landed
            __syncthreads();

            // ---- Compute slab j from buffer `cons` ----
            const uint32_t* ar = sm_ + A_OFF + cons * A_U32 + (mw * 16 + qr) * ASTRIDE + qc;

            #pragma unroll
            for (int kk = 0; kk < 2; ++kk) {     // two k16 steps cover 32 dims
                const int c = kk * 8;
                uint32_t a0 = ar[c];
                uint32_t a2 = ar[c + 4];
                uint32_t a1 = ar[c     + 8 * ASTRIDE];
                uint32_t a3 = ar[c + 4 + 8 * ASTRIDE];

                const uint32_t* wrow = ws + (j * 16 + kk * 8 + qc) * WSTRIDE + nh * 32 + qr;

                #pragma unroll
                for (int t = 0; t < 4; ++t) {
                    uint32_t b0 = wrow[t * 8];
                    uint32_t b1 = wrow[t * 8 + 4 * WSTRIDE];
                    asm volatile(
                        "mma.sync.aligned.m16n8k16.row.col.f32.f16.f16.f32 "
                        "{%0,%1,%2,%3}, {%4,%5,%6,%7}, {%8,%9}, {%0,%1,%2,%3};"
                        : "+f"(acc[t][0]), "+f"(acc[t][1]),
                          "+f"(acc[t][2]), "+f"(acc[t][3])
                        : "r"(a0), "r"(a1), "r"(a2), "r"(a3), "r"(b0), "r"(b1));
                }
            }
            __syncthreads();             // all warps done reading buffer `cons`

            // ---- Produce into the just-freed buffer (exactly one commit per j) ----
            uint32_t freed = sb + (A_OFF + cons * A_U32) * 4;
            if (j + 4 < FE) {
                gather_slab(sidx, j + 4, freed);
                if (j == 0 && has_next)  // fold next idx into this group; landed by j=5
                    stage_idx(nbr, tile + step, sb + (IDX_OFF + (ibuf ^ 1) * IDX_U32) * 4);
            } else if (has_next) {
                gather_slab(nsidx, j - 5, freed);   // next tile's slabs 0..3
            }
            cp_commit();                 // empty groups are fine; keeps wait<3> exact
            cons = (cons + 1) & 3;
        }

        // Epilogue: next tile's slabs 0..3 land underneath these stores.
        const int rowbase = tile * BLOCK_M;
        #pragma unroll
        for (int h = 0; h < 2; ++h) {
            int r = rowbase + mw * 16 + h * 8 + qr;
            if (r < NFINE) {
                float2* po = (float2*)(out + (size_t)r * NF + nh * 32 + qc * 2);
                #pragma unroll
                for (int t = 0; t < 4; ++t)
                    __stcs(po + t * 4, make_float2(acc[t][2*h], acc[t][2*h + 1]));
            }
        }
        ibuf ^= 1;
    }
}

extern "C" void kernel_launch(void* const* d_in, const int* in_sizes, int n_in,
                              void* d_out, int out_size)
{
    const float* coarse = (const float*)d_in[0];   // [250000, 32] f32
    const int*   nbr    = (const int*)  d_in[1];   // [1000000, 9] i32
    const float* weight = (const float*)d_in[2];   // [288, 64] f32
    float*       out    = (float*)d_out;           // [1000000, 64] f32

    cudaFuncSetAttribute(finefy_fp16_kernel,
                         cudaFuncAttributeMaxDynamicSharedMemorySize, SMEM_BYTES);

    int nsm = 148;
    cudaDeviceGetAttribute(&nsm, cudaDevAttrMultiProcessorCount, 0);

    // Pre-pass: convert coarse lattice to fp16 (deterministic, graph-capturable).
    conv_coarse<<<nsm * 4, 256>>>((const float4*)coarse);

    const int numTiles = (NFINE + BLOCK_M - 1) / BLOCK_M;   // 7813
    finefy_fp16_kernel<<<nsm * 2, THREADS, SMEM_BYTES>>>(nbr, weight, out, numTiles);
}

// round 10
// speedup vs baseline: 1.1136x; 1.0379x over previous
#include <cuda_runtime.h>
#include <cuda_fp16.h>
#include <cstdint>

#define NFINE   1000000
#define NCOARSE 250000
#define FE      9
#define NF      64
#define BLOCK_M 256
#define THREADS 512              // 16 warps: (wid&7)=m-tile(m32), (wid>>3)=n-half(n32)
#define WSTRIDE 72               // B half2-row stride (u32 words): conflict-free B LDS
#define ASTRIDE 20               // A row stride (u32 words): 64B data + 16B pad,
                                 // bank=(20qr+qc)%32 bijective -> conflict-free

// smem layout (u32 units)
#define WS_U32   (144 * WSTRIDE)           // 10368
#define A_OFF    WS_U32                    // 4 slab buffers (pipeline depth 4)
#define A_U32    (BLOCK_M * ASTRIDE)       // 5120 per slab buffer
#define IDX_OFF  (A_OFF + 4 * A_U32)       // 30848
#define IDX_U32  (BLOCK_M * FE)            // 2304 per idx buffer
#define SMEM_U32 (IDX_OFF + 2 * IDX_U32)   // 35456
#define SMEM_BYTES (SMEM_U32 * 4)          // 141824 B -> 1 CTA/SM

// fp16 copy of coarse values (filled by conv_coarse pre-pass each launch)
__device__ __half g_ch[NCOARSE * 32];      // 16 MB

__global__ void __launch_bounds__(256)
conv_coarse(const float4* __restrict__ src)
{
    uint2* dst = (uint2*)g_ch;
    const int n4 = NCOARSE * 8;
    for (int i = blockIdx.x * blockDim.x + threadIdx.x; i < n4;
         i += gridDim.x * blockDim.x) {
        float4 v = src[i];
        __half2 h0 = __floats2half2_rn(v.x, v.y);
        __half2 h1 = __floats2half2_rn(v.z, v.w);
        dst[i] = make_uint2(*(uint32_t*)&h0, *(uint32_t*)&h1);
    }
}

__device__ __forceinline__ void cp_commit() { asm volatile("cp.async.commit_group;"); }
template<int N> __device__ __forceinline__ void cp_wait() {
    asm volatile("cp.async.wait_group %0;" :: "n"(N));
}

// Gather one neighbor slab j: 256 rows x 64B, 2 cp.async(16B) per thread.
__device__ __forceinline__ void gather_slab(const int* __restrict__ sidx, int j,
                                            uint32_t abuf)
{
    #pragma unroll
    for (int i = 0; i < 2; ++i) {
        int o   = i * THREADS + threadIdx.x;   // 0..1023
        int r   = o >> 2;
        int seg = o & 3;
        int idx = sidx[r * FE + j];
        const char* src = (const char*)g_ch + ((size_t)(unsigned)idx << 6) + (seg << 4);
        uint32_t dst = abuf + (uint32_t)r * (ASTRIDE * 4) + (uint32_t)(seg << 4);
        asm volatile("cp.async.cg.shared.global [%0], [%1], 16;" :: "r"(dst), "l"(src));
    }
}

// Stage 256x9 neighbor indices for one tile (tail: clamp; stale rows stay valid).
__device__ __forceinline__ void stage_idx(const int* __restrict__ nbr, int tile,
                                          uint32_t dst)
{
    const size_t base = (size_t)tile * (BLOCK_M * FE);
    if (base + BLOCK_M * FE <= (size_t)NFINE * FE) {
        #pragma unroll
        for (int c = threadIdx.x; c < BLOCK_M * FE / 4; c += THREADS)
            asm volatile("cp.async.ca.shared.global [%0], [%1], 16;"
                         :: "r"(dst + c * 16), "l"(nbr + base + c * 4));
    } else {
        const size_t gmax = (size_t)NFINE * FE - 1;
        for (int i = threadIdx.x; i < BLOCK_M * FE; i += THREADS) {
            size_t g = base + i; if (g > gmax) g = gmax;
            asm volatile("cp.async.ca.shared.global [%0], [%1], 4;"
                         :: "r"(dst + i * 4), "l"(nbr + g));
        }
    }
}

__global__ void __launch_bounds__(THREADS, 1)
finefy_fp16_kernel(const int*   __restrict__ nbr,
                   const float* __restrict__ weight,
                   float*       __restrict__ out,
                   int numTiles)
{
    extern __shared__ uint32_t sm_[];
    uint32_t* ws = sm_;
    const uint32_t sb = (uint32_t)__cvta_generic_to_shared(sm_);

    const int tid  = threadIdx.x;
    const int lane = tid & 31;
    const int wid  = tid >> 5;
    const int qr   = lane >> 2;      // 0..7
    const int qc   = lane & 3;       // 0..3
    const int mw   = wid & 7;        // m-tile (rows mw*32..+31)
    const int nh   = wid >> 3;       // n-half (cols nh*32..+31)

    // Weight -> fp16, packed as half2 along K: B half index = (r*WSTRIDE+n)*2 + (k&1)
    for (int i = tid; i < 288 * NF; i += THREADS) {
        int k = i >> 6, n = i & 63;
        ((__half*)ws)[((k >> 1) * WSTRIDE + n) * 2 + (k & 1)] = __float2half_rn(weight[i]);
    }

    const int step = gridDim.x;
    int tile = blockIdx.x;
    int ibuf = 0;       // idx buffer holding current tile's indices
    int cons = 0;       // slab buffer about to be consumed (cycles mod 4)

    // ---- Prologue: stage idx for first tile, then fill the 4-deep slab pipe ----
    if (tile < numTiles) {
        stage_idx(nbr, tile, sb + IDX_OFF * 4);
        cp_commit(); cp_wait<0>(); __syncthreads();
        const int* sidx0 = (const int*)(sm_ + IDX_OFF);
        #pragma unroll
        for (int p = 0; p < 4; ++p) {
            gather_slab(sidx0, p, sb + (A_OFF + p * A_U32) * 4);
            cp_commit();
        }
    }

    for (; tile < numTiles; tile += step) {
        const int* sidx  = (const int*)(sm_ + IDX_OFF + ibuf * IDX_U32);
        const int* nsidx = (const int*)(sm_ + IDX_OFF + (ibuf ^ 1) * IDX_U32);
        const bool has_next = (tile + step) < numTiles;

        float acc[2][4][4];   // [m16-half][n8-tile][frag]
        #pragma unroll
        for (int i = 0; i < 2; ++i)
            #pragma unroll
            for (int t = 0; t < 4; ++t) {
                acc[i][t][0] = 0.f; acc[i][t][1] = 0.f;
                acc[i][t][2] = 0.f; acc[i][t][3] = 0.f;
            }

        #pragma unroll
        for (int j = 0; j < FE; ++j) {
            cp_wait<3>();                // slab j (oldest of 4 groups) landed
            __syncthreads();

            // ---- Compute slab j from buffer `cons`: warp tile m32 x n32 ----
            const uint32_t* ar0 = sm_ + A_OFF + cons * A_U32
                                  + (mw * 32 + qr) * ASTRIDE + qc;

            #pragma unroll
            for (int s2 = 0; s2 < 2; ++s2) {        // two m16 halves
                const uint32_t* ar = ar0 + s2 * 16 * ASTRIDE;
                #pragma unroll
                for (int kk = 0; kk < 2; ++kk) {     // two k16 steps cover 32 dims
                    const int c = kk * 8;
                    uint32_t a0 = ar[c];
                    uint32_t a2 = ar[c + 4];
                    uint32_t a1 = ar[c     + 8 * ASTRIDE];
                    uint32_t a3 = ar[c + 4 + 8 * ASTRIDE];

                    const uint32_t* wrow = ws + (j * 16 + kk * 8 + qc) * WSTRIDE
                                           + nh * 32 + qr;

                    #pragma unroll
                    for (int t = 0; t < 4; ++t) {
                        uint32_t b0 = wrow[t * 8];
                        uint32_t b1 = wrow[t * 8 + 4 * WSTRIDE];
                        asm volatile(
                            "mma.sync.aligned.m16n8k16.row.col.f32.f16.f16.f32 "
                            "{%0,%1,%2,%3}, {%4,%5,%6,%7}, {%8,%9}, {%0,%1,%2,%3};"
                            : "+f"(acc[s2][t][0]), "+f"(acc[s2][t][1]),
                              "+f"(acc[s2][t][2]), "+f"(acc[s2][t][3])
                            : "r"(a0), "r"(a1), "r"(a2), "r"(a3), "r"(b0), "r"(b1));
                    }
                }
            }
            __syncthreads();             // all warps done reading buffer `cons`

            // ---- Produce into the just-freed buffer (exactly one commit per j) ----
            uint32_t freed = sb + (A_OFF + cons * A_U32) * 4;
            if (j + 4 < FE) {
                gather_slab(sidx, j + 4, freed);
                if (j == 0 && has_next)  // fold next idx into this group; landed by j=5
                    stage_idx(nbr, tile + step, sb + (IDX_OFF + (ibuf ^ 1) * IDX_U32) * 4);
            } else if (has_next) {
                gather_slab(nsidx, j - 5, freed);   // next tile's slabs 0..3
            }
            cp_commit();                 // empty groups are fine; keeps wait<3> exact
            cons = (cons + 1) & 3;
        }

        // Epilogue: next tile's slabs 0..3 land underneath these stores.
        const int rowbase = tile * BLOCK_M;
        #pragma unroll
        for (int s2 = 0; s2 < 2; ++s2) {
            #pragma unroll
            for (int h = 0; h < 2; ++h) {
                int r = rowbase + mw * 32 + s2 * 16 + h * 8 + qr;
                if (r < NFINE) {
                    float2* po = (float2*)(out + (size_t)r * NF + nh * 32 + qc * 2);
                    #pragma unroll
                    for (int t = 0; t < 4; ++t)
                        __stcs(po + t * 4,
                               make_float2(acc[s2][t][2*h], acc[s2][t][2*h + 1]));
                }
            }
        }
        ibuf ^= 1;
    }
}

extern "C" void kernel_launch(void* const* d_in, const int* in_sizes, int n_in,
                              void* d_out, int out_size)
{
    const float* coarse = (const float*)d_in[0];   // [250000, 32] f32
    const int*   nbr    = (const int*)  d_in[1];   // [1000000, 9] i32
    const float* weight = (const float*)d_in[2];   // [288, 64] f32
    float*       out    = (float*)d_out;           // [1000000, 64] f32

    cudaFuncSetAttribute(finefy_fp16_kernel,
                         cudaFuncAttributeMaxDynamicSharedMemorySize, SMEM_BYTES);

    int nsm = 148;
    cudaDeviceGetAttribute(&nsm, cudaDevAttrMultiProcessorCount, 0);

    // Pre-pass: convert coarse lattice to fp16 (deterministic, graph-capturable).
    conv_coarse<<<nsm * 4, 256>>>((const float4*)coarse);

    const int numTiles = (NFINE + BLOCK_M - 1) / BLOCK_M;   // 3907
    finefy_fp16_kernel<<<nsm, THREADS, SMEM_BYTES>>>(nbr, weight, out, numTiles);
}

// round 11
// speedup vs baseline: 1.2984x; 1.1660x over previous
#include <cuda_runtime.h>
#include <cuda_fp16.h>
#include <cstdint>

#define NFINE   1000000
#define NCOARSE 250000
#define FE      9
#define NF      64
#define BLOCK_M 128              // per pipeline-group tile
#define THREADS 512              // 2 groups x 256 threads (8 warps each)
#define GTHREADS 256
#define NBUF    5                // slab buffers per group (produce-ahead 4)
#define WSTRIDE 72               // B half2-row stride (u32 words): conflict-free B LDS
#define ASTRIDE 20               // A row stride (u32 words): 64B data + 16B pad,
                                 // bank=(20qr+qc)%32 bijective -> conflict-free

// smem layout (u32 units)
#define WS_U32   (144 * WSTRIDE)               // 10368
#define A_U32    (BLOCK_M * ASTRIDE)           // 2560 per slab buffer
#define AG_U32   (NBUF * A_U32)                // 12800 per group
#define A_OFF(g)   (WS_U32 + (g) * AG_U32)
#define IDX_U32  (BLOCK_M * FE)                // 1152 per idx buffer
#define IDX_OFF(g) (WS_U32 + 2 * AG_U32 + (g) * 2 * IDX_U32)
#define SMEM_U32 (WS_U32 + 2 * AG_U32 + 4 * IDX_U32)   // 40576
#define SMEM_BYTES (SMEM_U32 * 4)              // 162304 B -> 1 CTA/SM

// fp16 copy of coarse values (filled by conv_coarse pre-pass each launch)
__device__ __half g_ch[NCOARSE * 32];          // 16 MB

__global__ void __launch_bounds__(256)
conv_coarse(const float4* __restrict__ src)
{
    uint2* dst = (uint2*)g_ch;
    const int n4 = NCOARSE * 8;
    for (int i = blockIdx.x * blockDim.x + threadIdx.x; i < n4;
         i += gridDim.x * blockDim.x) {
        float4 v = src[i];
        __half2 h0 = __floats2half2_rn(v.x, v.y);
        __half2 h1 = __floats2half2_rn(v.z, v.w);
        dst[i] = make_uint2(*(uint32_t*)&h0, *(uint32_t*)&h1);
    }
}

__device__ __forceinline__ void cp_commit() { asm volatile("cp.async.commit_group;"); }
template<int N> __device__ __forceinline__ void cp_wait() {
    asm volatile("cp.async.wait_group %0;" :: "n"(N));
}
__device__ __forceinline__ void gbar(int g) {   // 256-thread named barrier per group
    asm volatile("bar.sync %0, %1;" :: "r"(g + 1), "r"(GTHREADS) : "memory");
}

// Gather one neighbor slab j: 128 rows x 64B, 2 cp.async(16B) per group thread.
__device__ __forceinline__ void gather_slab(const int* __restrict__ sidx, int j,
                                            uint32_t abuf, int gtid)
{
    #pragma unroll
    for (int i = 0; i < 2; ++i) {
        int o   = i * GTHREADS + gtid;         // 0..511
        int r   = o >> 2;
        int seg = o & 3;
        int idx = sidx[r * FE + j];
        const char* src = (const char*)g_ch + ((size_t)(unsigned)idx << 6) + (seg << 4);
        uint32_t dst = abuf + (uint32_t)r * (ASTRIDE * 4) + (uint32_t)(seg << 4);
        asm volatile("cp.async.cg.shared.global [%0], [%1], 16;" :: "r"(dst), "l"(src));
    }
}

// Stage 128x9 neighbor indices for one tile (tail: per-element clamp, full coverage).
__device__ __forceinline__ void stage_idx(const int* __restrict__ nbr, int tile,
                                          uint32_t dst, int gtid)
{
    const size_t base = (size_t)tile * (BLOCK_M * FE);
    if (base + BLOCK_M * FE <= (size_t)NFINE * FE) {
        #pragma unroll
        for (int c = gtid; c < BLOCK_M * FE / 4; c += GTHREADS)
            asm volatile("cp.async.ca.shared.global [%0], [%1], 16;"
                         :: "r"(dst + c * 16), "l"(nbr + base + c * 4));
    } else {
        const size_t gmax = (size_t)NFINE * FE - 1;
        for (int i = gtid; i < BLOCK_M * FE; i += GTHREADS) {
            size_t g = base + i; if (g > gmax) g = gmax;
            asm volatile("cp.async.ca.shared.global [%0], [%1], 4;"
                         :: "r"(dst + i * 4), "l"(nbr + g));
        }
    }
}

__global__ void __launch_bounds__(THREADS, 1)
finefy_fp16_kernel(const int*   __restrict__ nbr,
                   const float* __restrict__ weight,
                   float*       __restrict__ out,
                   int numTiles)
{
    extern __shared__ uint32_t sm_[];
    uint32_t* ws = sm_;
    const uint32_t sb = (uint32_t)__cvta_generic_to_shared(sm_);

    const int tid  = threadIdx.x;
    const int grp  = tid >> 8;       // pipeline group 0/1
    const int gtid = tid & 255;
    const int lane = tid & 31;
    const int widg = gtid >> 5;      // warp within group: 0..7
    const int qr   = lane >> 2;      // 0..7
    const int qc   = lane & 3;       // 0..3
    const int mw   = widg & 3;       // m-tile (rows mw*32..+31 of 128)
    const int nh   = widg >> 2;      // n-half (cols nh*32..+31)

    // Weight -> fp16, packed as half2 along K (whole CTA cooperates, once).
    for (int i = tid; i < 288 * NF; i += THREADS) {
        int k = i >> 6, n = i & 63;
        ((__half*)ws)[((k >> 1) * WSTRIDE + n) * 2 + (k & 1)] = __float2half_rn(weight[i]);
    }
    __syncthreads();   // last CTA-wide barrier; groups run independently after this

    const uint32_t a_base   = sb + A_OFF(grp) * 4;
    const uint32_t idx_base = sb + IDX_OFF(grp) * 4;

    const int step = gridDim.x * 2;
    int tile = blockIdx.x * 2 + grp;
    int ibuf = 0;       // idx buffer holding current tile's indices
    int cons = 0;       // slab buffer about to be consumed (cycles mod 5)

    // ---- Prologue: stage idx, then fill 4 of the 5 slab buffers ----
    if (tile < numTiles) {
        stage_idx(nbr, tile, idx_base, gtid);
        cp_commit(); cp_wait<0>(); gbar(grp);
        const int* sidx0 = (const int*)(sm_ + IDX_OFF(grp));
        #pragma unroll
        for (int p = 0; p < 4; ++p) {
            gather_slab(sidx0, p, a_base + p * (A_U32 * 4), gtid);
            cp_commit();
        }
    }

    for (; tile < numTiles; tile += step) {
        const int* sidx  = (const int*)(sm_ + IDX_OFF(grp) + ibuf * IDX_U32);
        const int* nsidx = (const int*)(sm_ + IDX_OFF(grp) + (ibuf ^ 1) * IDX_U32);
        const bool has_next = (tile + step) < numTiles;

        float acc[2][4][4];   // [m16-half][n8-tile][frag]
        #pragma unroll
        for (int i = 0; i < 2; ++i)
            #pragma unroll
            for (int t = 0; t < 4; ++t) {
                acc[i][t][0] = 0.f; acc[i][t][1] = 0.f;
                acc[i][t][2] = 0.f; acc[i][t][3] = 0.f;
            }

        #pragma unroll
        for (int j = 0; j < FE; ++j) {
            cp_wait<3>();      // slab j (oldest of 4 pending groups) landed
            gbar(grp);         // also proves all warps finished slab j-1's buffer

            // ---- Produce slab j+4 into slab j-1's buffer ((cons+4)%5) ----
            uint32_t freed = a_base + ((cons + 4) % NBUF) * (A_U32 * 4);
            if (j + 4 < FE) {
                gather_slab(sidx, j + 4, freed, gtid);
                if (j == 0 && has_next)  // folded here; landed by j=4's wait -> used j=5
                    stage_idx(nbr, tile + step, idx_base + (ibuf ^ 1) * (IDX_U32 * 4), gtid);
            } else if (has_next) {
                gather_slab(nsidx, j - 5, freed, gtid);   // next tile's slabs 0..3
            }
            cp_commit();       // exactly one group per j (possibly empty)

            // ---- Compute slab j from buffer `cons`: warp tile m32 x n32 ----
            const uint32_t* ar0 = sm_ + A_OFF(grp) + cons * A_U32
                                  + (mw * 32 + qr) * ASTRIDE + qc;

            #pragma unroll
            for (int s2 = 0; s2 < 2; ++s2) {        // two m16 halves
                const uint32_t* ar = ar0 + s2 * 16 * ASTRIDE;
                #pragma unroll
                for (int kk = 0; kk < 2; ++kk) {     // two k16 steps cover 32 dims
                    const int c = kk * 8;
                    uint32_t a0 = ar[c];
                    uint32_t a2 = ar[c + 4];
                    uint32_t a1 = ar[c     + 8 * ASTRIDE];
                    uint32_t a3 = ar[c + 4 + 8 * ASTRIDE];

                    const uint32_t* wrow = ws + (j * 16 + kk * 8 + qc) * WSTRIDE
                                           + nh * 32 + qr;

                    #pragma unroll
                    for (int t = 0; t < 4; ++t) {
                        uint32_t b0 = wrow[t * 8];
                        uint32_t b1 = wrow[t * 8 + 4 * WSTRIDE];
                        asm volatile(
                            "mma.sync.aligned.m16n8k16.row.col.f32.f16.f16.f32 "
                            "{%0,%1,%2,%3}, {%4,%5,%6,%7}, {%8,%9}, {%0,%1,%2,%3};"
                            : "+f"(acc[s2][t][0]), "+f"(acc[s2][t][1]),
                              "+f"(acc[s2][t][2]), "+f"(acc[s2][t][3])
                            : "r"(a0), "r"(a1), "r"(a2), "r"(a3), "r"(b0), "r"(b1));
                    }
                }
            }
            cons = (cons + 1) % NBUF;
        }

        // Epilogue: next tile's slabs 0..3 land underneath these stores.
        const int rowbase = tile * BLOCK_M;
        #pragma unroll
        for (int s2 = 0; s2 < 2; ++s2) {
            #pragma unroll
            for (int h = 0; h < 2; ++h) {
                int r = rowbase + mw * 32 + s2 * 16 + h * 8 + qr;
                if (r < NFINE) {
                    float2* po = (float2*)(out + (size_t)r * NF + nh * 32 + qc * 2);
                    #pragma unroll
                    for (int t = 0; t < 4; ++t)
                        __stcs(po + t * 4,
                               make_float2(acc[s2][t][2*h], acc[s2][t][2*h + 1]));
                }
            }
        }
        ibuf ^= 1;
    }
}

extern "C" void kernel_launch(void* const* d_in, const int* in_sizes, int n_in,
                              void* d_out, int out_size)
{
    const float* coarse = (const float*)d_in[0];   // [250000, 32] f32
    const int*   nbr    = (const int*)  d_in[1];   // [1000000, 9] i32
    const float* weight = (const float*)d_in[2];   // [288, 64] f32
    float*       out    = (float*)d_out;           // [1000000, 64] f32

    cudaFuncSetAttribute(finefy_fp16_kernel,
                         cudaFuncAttributeMaxDynamicSharedMemorySize, SMEM_BYTES);

    int nsm = 148;
    cudaDeviceGetAttribute(&nsm, cudaDevAttrMultiProcessorCount, 0);

    // Pre-pass: convert coarse lattice to fp16 (deterministic, graph-capturable).
    conv_coarse<<<nsm * 4, 256>>>((const float4*)coarse);

    const int numTiles = (NFINE + BLOCK_M - 1) / BLOCK_M;   // 7813
    finefy_fp16_kernel<<<nsm, THREADS, SMEM_BYTES>>>(nbr, weight, out, numTiles);
}

// round 12
// speedup vs baseline: 1.3716x; 1.0563x over previous
#include <cuda_runtime.h>
#include <cuda_fp16.h>
#include <cstdint>

#define NFINE   1000000
#define NCOARSE 250000
#define FE      9
#define NF      64
#define BLOCK_M 128              // per pipeline-group tile
#define THREADS 512              // 2 groups x 256 threads (8 warps each)
#define GTHREADS 256
#define NBUF    5                // slab buffers per group (produce-ahead 4)
#define BSTRIDE 148              // B n-major row stride (u32 words) == 20 mod 32 ->
                                 // 8-row ldmatrix phases hit disjoint bank quads
#define ASTRIDE 20               // A row stride (u32 words): same conflict-free pattern

// smem layout (u32 units)
#define WS_U32   (NF * BSTRIDE)                // 9472 (W as [n][k] halves)
#define A_U32    (BLOCK_M * ASTRIDE)           // 2560 per slab buffer
#define AG_U32   (NBUF * A_U32)                // 12800 per group
#define A_OFF(g)   (WS_U32 + (g) * AG_U32)
#define IDX_U32  (BLOCK_M * FE)                // 1152 per idx buffer
#define IDX_OFF(g) (WS_U32 + 2 * AG_U32 + (g) * 2 * IDX_U32)
#define SMEM_U32 (WS_U32 + 2 * AG_U32 + 4 * IDX_U32)   // 39680
#define SMEM_BYTES (SMEM_U32 * 4)              // 158720 B -> 1 CTA/SM

// fp16 copy of coarse values (filled by conv_coarse pre-pass each launch)
__device__ __half g_ch[NCOARSE * 32];          // 16 MB

__global__ void __launch_bounds__(256)
conv_coarse(const float4* __restrict__ src)
{
    uint2* dst = (uint2*)g_ch;
    const int n4 = NCOARSE * 8;
    for (int i = blockIdx.x * blockDim.x + threadIdx.x; i < n4;
         i += gridDim.x * blockDim.x) {
        float4 v = src[i];
        __half2 h0 = __floats2half2_rn(v.x, v.y);
        __half2 h1 = __floats2half2_rn(v.z, v.w);
        dst[i] = make_uint2(*(uint32_t*)&h0, *(uint32_t*)&h1);
    }
}

__device__ __forceinline__ void cp_commit() { asm volatile("cp.async.commit_group;"); }
template<int N> __device__ __forceinline__ void cp_wait() {
    asm volatile("cp.async.wait_group %0;" :: "n"(N));
}
__device__ __forceinline__ void gbar(int g) {   // 256-thread named barrier per group
    asm volatile("bar.sync %0, %1;" :: "r"(g + 1), "r"(GTHREADS) : "memory");
}
__device__ __forceinline__ void ldsm_x4(uint32_t* r, uint32_t addr) {
    asm volatile("ldmatrix.sync.aligned.m8n8.x4.shared.b16 {%0,%1,%2,%3}, [%4];"
                 : "=r"(r[0]), "=r"(r[1]), "=r"(r[2]), "=r"(r[3]) : "r"(addr));
}

// Gather one neighbor slab j: 128 rows x 64B, 2 cp.async(16B) per group thread.
__device__ __forceinline__ void gather_slab(const int* __restrict__ sidx, int j,
                                            uint32_t abuf, int gtid)
{
    #pragma unroll
    for (int i = 0; i < 2; ++i) {
        int o   = i * GTHREADS + gtid;         // 0..511
        int r   = o >> 2;
        int seg = o & 3;
        int idx = sidx[r * FE + j];
        const char* src = (const char*)g_ch + ((size_t)(unsigned)idx << 6) + (seg << 4);
        uint32_t dst = abuf + (uint32_t)r * (ASTRIDE * 4) + (uint32_t)(seg << 4);
        asm volatile("cp.async.cg.shared.global [%0], [%1], 16;" :: "r"(dst), "l"(src));
    }
}

// Stage 128x9 neighbor indices for one tile (tail: per-element clamp).
__device__ __forceinline__ void stage_idx(const int* __restrict__ nbr, int tile,
                                          uint32_t dst, int gtid)
{
    const size_t base = (size_t)tile * (BLOCK_M * FE);
    if (base + BLOCK_M * FE <= (size_t)NFINE * FE) {
        #pragma unroll
        for (int c = gtid; c < BLOCK_M * FE / 4; c += GTHREADS)
            asm volatile("cp.async.ca.shared.global [%0], [%1], 16;"
                         :: "r"(dst + c * 16), "l"(nbr + base + c * 4));
    } else {
        const size_t gmax = (size_t)NFINE * FE - 1;
        for (int i = gtid; i < BLOCK_M * FE; i += GTHREADS) {
            size_t g = base + i; if (g > gmax) g = gmax;
            asm volatile("cp.async.ca.shared.global [%0], [%1], 4;"
                         :: "r"(dst + i * 4), "l"(nbr + g));
        }
    }
}

__global__ void __launch_bounds__(THREADS, 1)
finefy_fp16_kernel(const int*   __restrict__ nbr,
                   const float* __restrict__ weight,
                   float*       __restrict__ out,
                   int numTiles)
{
    extern __shared__ uint32_t sm_[];
    const uint32_t sb = (uint32_t)__cvta_generic_to_shared(sm_);

    const int tid  = threadIdx.x;
    const int grp  = tid >> 8;       // pipeline group 0/1
    const int gtid = tid & 255;
    const int lane = tid & 31;
    const int widg = gtid >> 5;      // warp within group: 0..7
    const int qr   = lane >> 2;      // 0..7
    const int qc   = lane & 3;       // 0..3
    const int mw   = widg & 3;       // m-tile (rows mw*32..+31 of 128)
    const int nh   = widg >> 2;      // n-half (cols nh*32..+31)

    // Weight -> fp16 n-major: half index = n*(BSTRIDE*2) + k. One-time scatter.
    for (int i = tid; i < 288 * NF; i += THREADS) {
        int k = i >> 6, n = i & 63;
        ((__half*)sm_)[n * (BSTRIDE * 2) + k] = __float2half_rn(weight[i]);
    }
    __syncthreads();   // last CTA-wide barrier; groups run independently after this

    const uint32_t a_base   = sb + A_OFF(grp) * 4;
    const uint32_t idx_base = sb + IDX_OFF(grp) * 4;

    // Per-lane ldmatrix address offsets (bytes).
    // A x4: lanes 0-7 m0-7/k-lo, 8-15 m8-15/k-lo, 16-23 m0-7/k-hi, 24-31 m8-15/k-hi
    const uint32_t a_lane_off = (((lane & 15) * ASTRIDE) + ((lane >> 4) * 4)) * 4;
    // B x4: lanes t*8..t*8+7 -> rows n = nh*32 + t*8 + (lane&7)
    const uint32_t b_lane_off = (uint32_t)(nh * 32 + ((lane >> 3) << 3) + (lane & 7))
                                * (BSTRIDE * 4);

    const int step = gridDim.x * 2;
    int tile = blockIdx.x * 2 + grp;
    int ibuf = 0;       // idx buffer holding current tile's indices
    int cons = 0;       // slab buffer about to be consumed (cycles mod 5)

    // ---- Prologue: stage idx, then fill 4 of the 5 slab buffers ----
    if (tile < numTiles) {
        stage_idx(nbr, tile, idx_base, gtid);
        cp_commit(); cp_wait<0>(); gbar(grp);
        const int* sidx0 = (const int*)(sm_ + IDX_OFF(grp));
        #pragma unroll
        for (int p = 0; p < 4; ++p) {
            gather_slab(sidx0, p, a_base + p * (A_U32 * 4), gtid);
            cp_commit();
        }
    }

    for (; tile < numTiles; tile += step) {
        const int* sidx  = (const int*)(sm_ + IDX_OFF(grp) + ibuf * IDX_U32);
        const int* nsidx = (const int*)(sm_ + IDX_OFF(grp) + (ibuf ^ 1) * IDX_U32);
        const bool has_next = (tile + step) < numTiles;

        float acc[2][4][4];   // [m16-half][n8-tile][frag]
        #pragma unroll
        for (int i = 0; i < 2; ++i)
            #pragma unroll
            for (int t = 0; t < 4; ++t) {
                acc[i][t][0] = 0.f; acc[i][t][1] = 0.f;
                acc[i][t][2] = 0.f; acc[i][t][3] = 0.f;
            }

        #pragma unroll
        for (int j = 0; j < FE; ++j) {
            cp_wait<3>();      // slab j (oldest of 4 pending groups) landed
            gbar(grp);         // also proves all warps finished slab j-1's buffer

            // ---- Produce slab j+4 into slab j-1's buffer ((cons+4)%5) ----
            uint32_t freed = a_base + ((cons + 4) % NBUF) * (A_U32 * 4);
            if (j + 4 < FE) {
                gather_slab(sidx, j + 4, freed, gtid);
                if (j == 0 && has_next)  // landed by j=4's wait; first used at j=5
                    stage_idx(nbr, tile + step, idx_base + (ibuf ^ 1) * (IDX_U32 * 4), gtid);
            } else if (has_next) {
                gather_slab(nsidx, j - 5, freed, gtid);   // next tile's slabs 0..3
            }
            cp_commit();       // exactly one group per j (possibly empty)

            // ---- Compute slab j from buffer `cons`: warp tile m32 x n32 ----
            const uint32_t a_slab = a_base + cons * (A_U32 * 4)
                                    + (uint32_t)(mw * 32) * (ASTRIDE * 4) + a_lane_off;
            const uint32_t b_slab = sb + b_lane_off + (uint32_t)j * 64;  // j*32 halves

            #pragma unroll
            for (int kk = 0; kk < 2; ++kk) {     // two k16 steps cover 32 dims
                uint32_t bl[4], bh[4];
                ldsm_x4(bl, b_slab + kk * 32);        // b0 for t=0..3 (k lo 8)
                ldsm_x4(bh, b_slab + kk * 32 + 16);   // b1 for t=0..3 (k hi 8)

                #pragma unroll
                for (int s2 = 0; s2 < 2; ++s2) { // two m16 halves
                    uint32_t a[4];
                    ldsm_x4(a, a_slab + (uint32_t)(s2 * 16 * ASTRIDE + kk * 8) * 4);

                    #pragma unroll
                    for (int t = 0; t < 4; ++t) {
                        asm volatile(
                            "mma.sync.aligned.m16n8k16.row.col.f32.f16.f16.f32 "
                            "{%0,%1,%2,%3}, {%4,%5,%6,%7}, {%8,%9}, {%0,%1,%2,%3};"
                            : "+f"(acc[s2][t][0]), "+f"(acc[s2][t][1]),
                              "+f"(acc[s2][t][2]), "+f"(acc[s2][t][3])
                            : "r"(a[0]), "r"(a[1]), "r"(a[2]), "r"(a[3]),
                              "r"(bl[t]), "r"(bh[t]));
                    }
                }
            }
            cons = (cons + 1) % NBUF;
        }

        // Epilogue: next tile's slabs 0..3 land underneath these stores.
        const int rowbase = tile * BLOCK_M;
        #pragma unroll
        for (int s2 = 0; s2 < 2; ++s2) {
            #pragma unroll
            for (int h = 0; h < 2; ++h) {
                int r = rowbase + mw * 32 + s2 * 16 + h * 8 + qr;
                if (r < NFINE) {
                    float2* po = (float2*)(out + (size_t)r * NF + nh * 32 + qc * 2);
                    #pragma unroll
                    for (int t = 0; t < 4; ++t)
                        __stcs(po + t * 4,
                               make_float2(acc[s2][t][2*h], acc[s2][t][2*h + 1]));
                }
            }
        }
        ibuf ^= 1;
    }
}

extern "C" void kernel_launch(void* const* d_in, const int* in_sizes, int n_in,
                              void* d_out, int out_size)
{
    const float* coarse = (const float*)d_in[0];   // [250000, 32] f32
    const int*   nbr    = (const int*)  d_in[1];   // [1000000, 9] i32
    const float* weight = (const float*)d_in[2];   // [288, 64] f32
    float*       out    = (float*)d_out;           // [1000000, 64] f32

    cudaFuncSetAttribute(finefy_fp16_kernel,
                         cudaFuncAttributeMaxDynamicSharedMemorySize, SMEM_BYTES);

    int nsm = 148;
    cudaDeviceGetAttribute(&nsm, cudaDevAttrMultiProcessorCount, 0);

    // Pre-pass: convert coarse lattice to fp16 (deterministic, graph-capturable).
    conv_coarse<<<nsm * 4, 256>>>((const float4*)coarse);

    const int numTiles = (NFINE + BLOCK_M - 1) / BLOCK_M;   // 7813
    finefy_fp16_kernel<<<nsm, THREADS, SMEM_BYTES>>>(nbr, weight, out, numTiles);
}

// round 13
// speedup vs baseline: 1.4604x; 1.0647x over previous
#include <cuda_runtime.h>
#include <cuda_fp16.h>
#include <cstdint>

#define NFINE   1000000
#define NCOARSE 250000
#define FE      9
#define NF      64
#define BLOCK_M 64               // per pipeline-group tile
#define THREADS 512              // 4 groups x 128 threads (4 warps each)
#define GTHREADS 128
#define NGRP    4
#define NBUF    5                // slab buffers per group (produce-ahead 4)
#define BSTRIDE 148              // B n-major row stride (u32 words) == 20 mod 32 ->
                                 // 8-row ldmatrix phases hit disjoint bank quads
#define ASTRIDE 20               // A row stride (u32 words): same conflict-free pattern

// smem layout (u32 units)
#define WS_U32   (NF * BSTRIDE)                // 9472 (W as [n][k] halves, shared)
#define A_U32    (BLOCK_M * ASTRIDE)           // 1280 per slab buffer
#define AG_U32   (NBUF * A_U32)                // 6400 per group
#define A_OFF(g)   (WS_U32 + (g) * AG_U32)
#define IDX_U32  (BLOCK_M * FE)                // 576 per idx buffer
#define IDX_OFF(g) (WS_U32 + NGRP * AG_U32 + (g) * 2 * IDX_U32)
#define SMEM_U32 (WS_U32 + NGRP * AG_U32 + NGRP * 2 * IDX_U32)  // 39680
#define SMEM_BYTES (SMEM_U32 * 4)              // 158720 B -> 1 CTA/SM

// fp16 copy of coarse values (filled by conv_coarse pre-pass each launch)
__device__ __half g_ch[NCOARSE * 32];          // 16 MB

__global__ void __launch_bounds__(256)
conv_coarse(const float4* __restrict__ src)
{
    uint2* dst = (uint2*)g_ch;
    const int n4 = NCOARSE * 8;
    for (int i = blockIdx.x * blockDim.x + threadIdx.x; i < n4;
         i += gridDim.x * blockDim.x) {
        float4 v = src[i];
        __half2 h0 = __floats2half2_rn(v.x, v.y);
        __half2 h1 = __floats2half2_rn(v.z, v.w);
        dst[i] = make_uint2(*(uint32_t*)&h0, *(uint32_t*)&h1);
    }
}

__device__ __forceinline__ void cp_commit() { asm volatile("cp.async.commit_group;"); }
template<int N> __device__ __forceinline__ void cp_wait() {
    asm volatile("cp.async.wait_group %0;" :: "n"(N));
}
__device__ __forceinline__ void gbar(int g) {   // 128-thread named barrier per group
    asm volatile("bar.sync %0, %1;" :: "r"(g + 1), "r"(GTHREADS) : "memory");
}
__device__ __forceinline__ void ldsm_x4(uint32_t* r, uint32_t addr) {
    asm volatile("ldmatrix.sync.aligned.m8n8.x4.shared.b16 {%0,%1,%2,%3}, [%4];"
                 : "=r"(r[0]), "=r"(r[1]), "=r"(r[2]), "=r"(r[3]) : "r"(addr));
}

// Gather one neighbor slab j: 64 rows x 64B, 2 cp.async(16B) per group thread.
__device__ __forceinline__ void gather_slab(const int* __restrict__ sidx, int j,
                                            uint32_t abuf, int gtid)
{
    #pragma unroll
    for (int i = 0; i < 2; ++i) {
        int o   = i * GTHREADS + gtid;         // 0..255
        int r   = o >> 2;
        int seg = o & 3;
        int idx = sidx[r * FE + j];
        const char* src = (const char*)g_ch + ((size_t)(unsigned)idx << 6) + (seg << 4);
        uint32_t dst = abuf + (uint32_t)r * (ASTRIDE * 4) + (uint32_t)(seg << 4);
        asm volatile("cp.async.cg.shared.global [%0], [%1], 16;" :: "r"(dst), "l"(src));
    }
}

// Stage 64x9 neighbor indices for one tile (tail: per-element clamp).
__device__ __forceinline__ void stage_idx(const int* __restrict__ nbr, int tile,
                                          uint32_t dst, int gtid)
{
    const size_t base = (size_t)tile * (BLOCK_M * FE);
    if (base + BLOCK_M * FE <= (size_t)NFINE * FE) {
        #pragma unroll
        for (int c = gtid; c < BLOCK_M * FE / 4; c += GTHREADS)
            asm volatile("cp.async.ca.shared.global [%0], [%1], 16;"
                         :: "r"(dst + c * 16), "l"(nbr + base + c * 4));
    } else {
        const size_t gmax = (size_t)NFINE * FE - 1;
        for (int i = gtid; i < BLOCK_M * FE; i += GTHREADS) {
            size_t g = base + i; if (g > gmax) g = gmax;
            asm volatile("cp.async.ca.shared.global [%0], [%1], 4;"
                         :: "r"(dst + i * 4), "l"(nbr + g));
        }
    }
}

__global__ void __launch_bounds__(THREADS, 1)
finefy_fp16_kernel(const int*   __restrict__ nbr,
                   const float* __restrict__ weight,
                   float*       __restrict__ out,
                   int numTiles)
{
    extern __shared__ uint32_t sm_[];
    const uint32_t sb = (uint32_t)__cvta_generic_to_shared(sm_);

    const int tid  = threadIdx.x;
    const int grp  = tid >> 7;       // pipeline group 0..3
    const int gtid = tid & 127;
    const int lane = tid & 31;
    const int widg = gtid >> 5;      // warp within group: 0..3
    const int qr   = lane >> 2;      // 0..7
    const int qc   = lane & 3;       // 0..3
    const int mw   = widg & 1;       // m-tile (rows mw*32..+31 of 64)
    const int nh   = widg >> 1;      // n-half (cols nh*32..+31)

    // Weight -> fp16 n-major: half index = n*(BSTRIDE*2) + k. One-time scatter.
    for (int i = tid; i < 288 * NF; i += THREADS) {
        int k = i >> 6, n = i & 63;
        ((__half*)sm_)[n * (BSTRIDE * 2) + k] = __float2half_rn(weight[i]);
    }
    __syncthreads();   // last CTA-wide barrier; groups run independently after this

    const uint32_t a_base   = sb + A_OFF(grp) * 4;
    const uint32_t idx_base = sb + IDX_OFF(grp) * 4;

    // Per-lane ldmatrix address offsets (bytes).
    const uint32_t a_lane_off = (((lane & 15) * ASTRIDE) + ((lane >> 4) * 4)) * 4;
    const uint32_t b_lane_off = (uint32_t)(nh * 32 + ((lane >> 3) << 3) + (lane & 7))
                                * (BSTRIDE * 4);

    const int step = gridDim.x * NGRP;
    int tile = blockIdx.x * NGRP + grp;
    int ibuf = 0;       // idx buffer holding current tile's indices
    int cons = 0;       // slab buffer about to be consumed (cycles mod 5)

    // ---- Prologue: stage idx, then fill 4 of the 5 slab buffers ----
    if (tile < numTiles) {
        stage_idx(nbr, tile, idx_base, gtid);
        cp_commit(); cp_wait<0>(); gbar(grp);
        const int* sidx0 = (const int*)(sm_ + IDX_OFF(grp));
        #pragma unroll
        for (int p = 0; p < 4; ++p) {
            gather_slab(sidx0, p, a_base + p * (A_U32 * 4), gtid);
            cp_commit();
        }
    }

    for (; tile < numTiles; tile += step) {
        const int* sidx  = (const int*)(sm_ + IDX_OFF(grp) + ibuf * IDX_U32);
        const int* nsidx = (const int*)(sm_ + IDX_OFF(grp) + (ibuf ^ 1) * IDX_U32);
        const bool has_next = (tile + step) < numTiles;

        float acc[2][4][4];   // [m16-half][n8-tile][frag]
        #pragma unroll
        for (int i = 0; i < 2; ++i)
            #pragma unroll
            for (int t = 0; t < 4; ++t) {
                acc[i][t][0] = 0.f; acc[i][t][1] = 0.f;
                acc[i][t][2] = 0.f; acc[i][t][3] = 0.f;
            }

        #pragma unroll
        for (int j = 0; j < FE; ++j) {
            cp_wait<3>();      // slab j (oldest of 4 pending groups) landed
            gbar(grp);         // also proves all warps finished slab j-1's buffer

            // ---- Produce slab j+4 into slab j-1's buffer ((cons+4)%5) ----
            uint32_t freed = a_base + ((cons + 4) % NBUF) * (A_U32 * 4);
            if (j + 4 < FE) {
                gather_slab(sidx, j + 4, freed, gtid);
                if (j == 0 && has_next)  // landed by j=4's wait; first used at j=5
                    stage_idx(nbr, tile + step, idx_base + (ibuf ^ 1) * (IDX_U32 * 4), gtid);
            } else if (has_next) {
                gather_slab(nsidx, j - 5, freed, gtid);   // next tile's slabs 0..3
            }
            cp_commit();       // exactly one group per j (possibly empty)

            // ---- Compute slab j from buffer `cons`: warp tile m32 x n32 ----
            const uint32_t a_slab = a_base + cons * (A_U32 * 4)
                                    + (uint32_t)(mw * 32) * (ASTRIDE * 4) + a_lane_off;
            const uint32_t b_slab = sb + b_lane_off + (uint32_t)j * 64;  // j*32 halves

            #pragma unroll
            for (int kk = 0; kk < 2; ++kk) {     // two k16 steps cover 32 dims
                uint32_t bl[4], bh[4];
                ldsm_x4(bl, b_slab + kk * 32);        // b0 for t=0..3 (k lo 8)
                ldsm_x4(bh, b_slab + kk * 32 + 16);   // b1 for t=0..3 (k hi 8)

                #pragma unroll
                for (int s2 = 0; s2 < 2; ++s2) { // two m16 halves
                    uint32_t a[4];
                    ldsm_x4(a, a_slab + (uint32_t)(s2 * 16 * ASTRIDE + kk * 8) * 4);

                    #pragma unroll
                    for (int t = 0; t < 4; ++t) {
                        asm volatile(
                            "mma.sync.aligned.m16n8k16.row.col.f32.f16.f16.f32 "
                            "{%0,%1,%2,%3}, {%4,%5,%6,%7}, {%8,%9}, {%0,%1,%2,%3};"
                            : "+f"(acc[s2][t][0]), "+f"(acc[s2][t][1]),
                              "+f"(acc[s2][t][2]), "+f"(acc[s2][t][3])
                            : "r"(a[0]), "r"(a[1]), "r"(a[2]), "r"(a[3]),
                              "r"(bl[t]), "r"(bh[t]));
                    }
                }
            }
            cons = (cons + 1) % NBUF;
        }

        // Epilogue: next tile's slabs 0..3 land underneath these stores.
        const int rowbase = tile * BLOCK_M;
        #pragma unroll
        for (int s2 = 0; s2 < 2; ++s2) {
            #pragma unroll
            for (int h = 0; h < 2; ++h) {
                int r = rowbase + mw * 32 + s2 * 16 + h * 8 + qr;
                if (r < NFINE) {
                    float2* po = (float2*)(out + (size_t)r * NF + nh * 32 + qc * 2);
                    #pragma unroll
                    for (int t = 0; t < 4; ++t)
                        __stcs(po + t * 4,
                               make_float2(acc[s2][t][2*h], acc[s2][t][2*h + 1]));
                }
            }
        }
        ibuf ^= 1;
    }
}

extern "C" void kernel_launch(void* const* d_in, const int* in_sizes, int n_in,
                              void* d_out, int out_size)
{
    const float* coarse = (const float*)d_in[0];   // [250000, 32] f32
    const int*   nbr    = (const int*)  d_in[1];   // [1000000, 9] i32
    const float* weight = (const float*)d_in[2];   // [288, 64] f32
    float*       out    = (float*)d_out;           // [1000000, 64] f32

    cudaFuncSetAttribute(finefy_fp16_kernel,
                         cudaFuncAttributeMaxDynamicSharedMemorySize, SMEM_BYTES);

    int nsm = 148;
    cudaDeviceGetAttribute(&nsm, cudaDevAttrMultiProcessorCount, 0);

    // Pre-pass: convert coarse lattice to fp16 (deterministic, graph-capturable).
    conv_coarse<<<nsm * 4, 256>>>((const float4*)coarse);

    const int numTiles = (NFINE + BLOCK_M - 1) / BLOCK_M;   // 15625
    finefy_fp16_kernel<<<nsm, THREADS, SMEM_BYTES>>>(nbr, weight, out, numTiles);
}

// round 14
// speedup vs baseline: 1.5315x; 1.0487x over previous
#include <cuda_runtime.h>
#include <cuda_fp16.h>
#include <cstdint>

#define NFINE   1000000
#define NCOARSE 250000
#define FE      9
#define NF      64
#define BLOCK_M 128              // per pipeline-group tile
#define THREADS 512              // 4 groups x 128 threads (4 warps each)
#define GTHREADS 128
#define NGRP    4
#define NBUF    3                // slab buffers per group (produce-ahead 2)
#define BSTRIDE 148              // B n-major row stride (u32 words) == 20 mod 32 ->
                                 // 8-row ldmatrix phases hit disjoint bank quads
#define ASTRIDE 20               // A row stride (u32 words): same conflict-free pattern

// smem layout (u32 units)
#define WS_U32   (NF * BSTRIDE)                // 9472 (W as [n][k] halves, shared)
#define A_U32    (BLOCK_M * ASTRIDE)           // 2560 per slab buffer
#define AG_U32   (NBUF * A_U32)                // 7680 per group
#define A_OFF(g)   (WS_U32 + (g) * AG_U32)
#define IDX_U32  (BLOCK_M * FE)                // 1152 per idx buffer
#define IDX_OFF(g) (WS_U32 + NGRP * AG_U32 + (g) * 2 * IDX_U32)
#define SMEM_U32 (WS_U32 + NGRP * AG_U32 + NGRP * 2 * IDX_U32)  // 49408
#define SMEM_BYTES (SMEM_U32 * 4)              // 197632 B -> 1 CTA/SM

// fp16 copy of coarse values (filled by conv_coarse pre-pass each launch)
__device__ __half g_ch[NCOARSE * 32];          // 16 MB

__global__ void __launch_bounds__(256)
conv_coarse(const float4* __restrict__ src)
{
    uint2* dst = (uint2*)g_ch;
    const int n4 = NCOARSE * 8;
    for (int i = blockIdx.x * blockDim.x + threadIdx.x; i < n4;
         i += gridDim.x * blockDim.x) {
        float4 v = src[i];
        __half2 h0 = __floats2half2_rn(v.x, v.y);
        __half2 h1 = __floats2half2_rn(v.z, v.w);
        dst[i] = make_uint2(*(uint32_t*)&h0, *(uint32_t*)&h1);
    }
}

__device__ __forceinline__ void cp_commit() { asm volatile("cp.async.commit_group;"); }
template<int N> __device__ __forceinline__ void cp_wait() {
    asm volatile("cp.async.wait_group %0;" :: "n"(N));
}
__device__ __forceinline__ void gbar(int g) {   // 128-thread named barrier per group
    asm volatile("bar.sync %0, %1;" :: "r"(g + 1), "r"(GTHREADS) : "memory");
}
__device__ __forceinline__ void ldsm_x4(uint32_t* r, uint32_t addr) {
    asm volatile("ldmatrix.sync.aligned.m8n8.x4.shared.b16 {%0,%1,%2,%3}, [%4];"
                 : "=r"(r[0]), "=r"(r[1]), "=r"(r[2]), "=r"(r[3]) : "r"(addr));
}

// Gather one neighbor slab j: 128 rows x 64B, 4 cp.async(16B) per group thread.
__device__ __forceinline__ void gather_slab(const int* __restrict__ sidx, int j,
                                            uint32_t abuf, int gtid)
{
    #pragma unroll
    for (int i = 0; i < 4; ++i) {
        int o   = i * GTHREADS + gtid;         // 0..511
        int r   = o >> 2;
        int seg = o & 3;
        int idx = sidx[r * FE + j];
        const char* src = (const char*)g_ch + ((size_t)(unsigned)idx << 6) + (seg << 4);
        uint32_t dst = abuf + (uint32_t)r * (ASTRIDE * 4) + (uint32_t)(seg << 4);
        asm volatile("cp.async.cg.shared.global [%0], [%1], 16;" :: "r"(dst), "l"(src));
    }
}

// Stage 128x9 neighbor indices for one tile (tail: per-element clamp).
__device__ __forceinline__ void stage_idx(const int* __restrict__ nbr, int tile,
                                          uint32_t dst, int gtid)
{
    const size_t base = (size_t)tile * (BLOCK_M * FE);
    if (base + BLOCK_M * FE <= (size_t)NFINE * FE) {
        #pragma unroll
        for (int c = gtid; c < BLOCK_M * FE / 4; c += GTHREADS)
            asm volatile("cp.async.ca.shared.global [%0], [%1], 16;"
                         :: "r"(dst + c * 16), "l"(nbr + base + c * 4));
    } else {
        const size_t gmax = (size_t)NFINE * FE - 1;
        for (int i = gtid; i < BLOCK_M * FE; i += GTHREADS) {
            size_t g = base + i; if (g > gmax) g = gmax;
            asm volatile("cp.async.ca.shared.global [%0], [%1], 4;"
                         :: "r"(dst + i * 4), "l"(nbr + g));
        }
    }
}

__global__ void __launch_bounds__(THREADS, 1)
finefy_fp16_kernel(const int*   __restrict__ nbr,
                   const float* __restrict__ weight,
                   float*       __restrict__ out,
                   int numTiles)
{
    extern __shared__ uint32_t sm_[];
    const uint32_t sb = (uint32_t)__cvta_generic_to_shared(sm_);

    const int tid  = threadIdx.x;
    const int grp  = tid >> 7;       // pipeline group 0..3
    const int gtid = tid & 127;
    const int lane = tid & 31;
    const int widg = gtid >> 5;      // warp within group: 0..3
    const int qr   = lane >> 2;      // 0..7
    const int qc   = lane & 3;       // 0..3
    const int mw   = widg & 1;       // m-tile (rows mw*64..+63 of 128)
    const int nh   = widg >> 1;      // n-half (cols nh*32..+31)

    // Weight -> fp16 n-major: half index = n*(BSTRIDE*2) + k. One-time scatter.
    for (int i = tid; i < 288 * NF; i += THREADS) {
        int k = i >> 6, n = i & 63;
        ((__half*)sm_)[n * (BSTRIDE * 2) + k] = __float2half_rn(weight[i]);
    }
    __syncthreads();   // last CTA-wide barrier; groups run independently after this

    const uint32_t a_base   = sb + A_OFF(grp) * 4;
    const uint32_t idx_base = sb + IDX_OFF(grp) * 4;

    // Per-lane ldmatrix address offsets (bytes).
    const uint32_t a_lane_off = (((lane & 15) * ASTRIDE) + ((lane >> 4) * 4)) * 4;
    const uint32_t b_lane_off = (uint32_t)(nh * 32 + ((lane >> 3) << 3) + (lane & 7))
                                * (BSTRIDE * 4);

    const int step = gridDim.x * NGRP;
    int tile = blockIdx.x * NGRP + grp;
    int ibuf = 0;       // idx buffer holding current tile's indices
    int cons = 0;       // slab buffer about to be consumed (cycles mod 3)

    // ---- Prologue: stage idx, then fill 2 of the 3 slab buffers ----
    if (tile < numTiles) {
        stage_idx(nbr, tile, idx_base, gtid);
        cp_commit(); cp_wait<0>(); gbar(grp);
        const int* sidx0 = (const int*)(sm_ + IDX_OFF(grp));
        #pragma unroll
        for (int p = 0; p < 2; ++p) {
            gather_slab(sidx0, p, a_base + p * (A_U32 * 4), gtid);
            cp_commit();
        }
    }

    for (; tile < numTiles; tile += step) {
        const int* sidx  = (const int*)(sm_ + IDX_OFF(grp) + ibuf * IDX_U32);
        const int* nsidx = (const int*)(sm_ + IDX_OFF(grp) + (ibuf ^ 1) * IDX_U32);
        const bool has_next = (tile + step) < numTiles;

        float acc[4][4][4];   // [m16-quarter][n8-tile][frag]
        #pragma unroll
        for (int i = 0; i < 4; ++i)
            #pragma unroll
            for (int t = 0; t < 4; ++t) {
                acc[i][t][0] = 0.f; acc[i][t][1] = 0.f;
                acc[i][t][2] = 0.f; acc[i][t][3] = 0.f;
            }

        #pragma unroll
        for (int j = 0; j < FE; ++j) {
            cp_wait<1>();      // slab j landed (only slab j+1's group still pending)
            gbar(grp);         // also proves all warps finished slab j-1's buffer

            // ---- Produce slab j+2 into slab j-1's buffer ((cons+2)%3) ----
            uint32_t freed = a_base + ((cons + 2) % NBUF) * (A_U32 * 4);
            if (j + 2 < FE) {
                gather_slab(sidx, j + 2, freed, gtid);
                if (j == 0 && has_next)  // lands by j=2's wait; first used at j=7
                    stage_idx(nbr, tile + step, idx_base + (ibuf ^ 1) * (IDX_U32 * 4), gtid);
            } else if (has_next) {
                gather_slab(nsidx, j - 7, freed, gtid);   // next tile's slabs 0..1
            }
            cp_commit();       // exactly one group per j (possibly empty)

            // ---- Compute slab j from buffer `cons`: warp tile m64 x n32 ----
            const uint32_t a_slab = a_base + cons * (A_U32 * 4)
                                    + (uint32_t)(mw * 64) * (ASTRIDE * 4) + a_lane_off;
            const uint32_t b_slab = sb + b_lane_off + (uint32_t)j * 64;  // j*32 halves

            #pragma unroll
            for (int kk = 0; kk < 2; ++kk) {     // two k16 steps cover 32 dims
                uint32_t bl[4], bh[4];
                ldsm_x4(bl, b_slab + kk * 32);        // b0 for t=0..3 (k lo 8)
                ldsm_x4(bh, b_slab + kk * 32 + 16);   // b1 for t=0..3 (k hi 8)

                #pragma unroll
                for (int s2 = 0; s2 < 4; ++s2) { // four m16 quarters of m64
                    uint32_t a[4];
                    ldsm_x4(a, a_slab + (uint32_t)(s2 * 16 * ASTRIDE + kk * 8) * 4);

                    #pragma unroll
                    for (int t = 0; t < 4; ++t) {
                        asm volatile(
                            "mma.sync.aligned.m16n8k16.row.col.f32.f16.f16.f32 "
                            "{%0,%1,%2,%3}, {%4,%5,%6,%7}, {%8,%9}, {%0,%1,%2,%3};"
                            : "+f"(acc[s2][t][0]), "+f"(acc[s2][t][1]),
                              "+f"(acc[s2][t][2]), "+f"(acc[s2][t][3])
                            : "r"(a[0]), "r"(a[1]), "r"(a[2]), "r"(a[3]),
                              "r"(bl[t]), "r"(bh[t]));
                    }
                }
            }
            cons = (cons + 1) % NBUF;
        }

        // Epilogue: next tile's slabs 0..1 land underneath these stores.
        const int rowbase = tile * BLOCK_M;
        #pragma unroll
        for (int s2 = 0; s2 < 4; ++s2) {
            #pragma unroll
            for (int h = 0; h < 2; ++h) {
                int r = rowbase + mw * 64 + s2 * 16 + h * 8 + qr;
                if (r < NFINE) {
                    float2* po = (float2*)(out + (size_t)r * NF + nh * 32 + qc * 2);
                    #pragma unroll
                    for (int t = 0; t < 4; ++t)
                        __stcs(po + t * 4,
                               make_float2(acc[s2][t][2*h], acc[s2][t][2*h + 1]));
                }
            }
        }
        ibuf ^= 1;
    }
}

extern "C" void kernel_launch(void* const* d_in, const int* in_sizes, int n_in,
                              void* d_out, int out_size)
{
    const float* coarse = (const float*)d_in[0];   // [250000, 32] f32
    const int*   nbr    = (const int*)  d_in[1];   // [1000000, 9] i32
    const float* weight = (const float*)d_in[2];   // [288, 64] f32
    float*       out    = (float*)d_out;           // [1000000, 64] f32

    cudaFuncSetAttribute(finefy_fp16_kernel,
                         cudaFuncAttributeMaxDynamicSharedMemorySize, SMEM_BYTES);

    int nsm = 148;
    cudaDeviceGetAttribute(&nsm, cudaDevAttrMultiProcessorCount, 0);

    // Pre-pass: convert coarse lattice to fp16 (deterministic, graph-capturable).
    conv_coarse<<<nsm * 4, 256>>>((const float4*)coarse);

    const int numTiles = (NFINE + BLOCK_M - 1) / BLOCK_M;   // 7813
    finefy_fp16_kernel<<<nsm, THREADS, SMEM_BYTES>>>(nbr, weight, out, numTiles);
}

// round 15
// speedup vs baseline: 1.5434x; 1.0078x over previous
#include <cuda_runtime.h>
#include <cuda_fp16.h>
#include <cstdint>

#define NFINE   1000000
#define NCOARSE 250000
#define FE      9
#define NF      64
#define BLOCK_M 64               // per pipeline-group tile
#define THREADS 512              // 8 groups x 64 threads (2 warps each)
#define GTHREADS 64
#define NGRP    8
#define NBUF    3                // slab buffers per group (produce-ahead 2)
#define BSTRIDE 148              // B n-major row stride (u32 words) == 20 mod 32 ->
                                 // 8-row ldmatrix phases hit disjoint bank quads
#define ASTRIDE 20               // A row stride (u32 words): same conflict-free pattern

// smem layout (u32 units)
#define WS_U32   (NF * BSTRIDE)                // 9472 (W as [n][k] halves, shared)
#define A_U32    (BLOCK_M * ASTRIDE)           // 1280 per slab buffer
#define AG_U32   (NBUF * A_U32)                // 3840 per group
#define A_OFF(g)   (WS_U32 + (g) * AG_U32)
#define IDX_U32  (BLOCK_M * FE)                // 576 per idx buffer
#define IDX_OFF(g) (WS_U32 + NGRP * AG_U32 + (g) * 2 * IDX_U32)
#define SMEM_U32 (WS_U32 + NGRP * AG_U32 + NGRP * 2 * IDX_U32)  // 49408
#define SMEM_BYTES (SMEM_U32 * 4)              // 197632 B -> 1 CTA/SM

// fp16 copy of coarse values (filled by conv_coarse pre-pass each launch)
__device__ __half g_ch[NCOARSE * 32];          // 16 MB

__global__ void __launch_bounds__(256)
conv_coarse(const float4* __restrict__ src)
{
    uint2* dst = (uint2*)g_ch;
    const int n4 = NCOARSE * 8;
    for (int i = blockIdx.x * blockDim.x + threadIdx.x; i < n4;
         i += gridDim.x * blockDim.x) {
        float4 v = src[i];
        __half2 h0 = __floats2half2_rn(v.x, v.y);
        __half2 h1 = __floats2half2_rn(v.z, v.w);
        dst[i] = make_uint2(*(uint32_t*)&h0, *(uint32_t*)&h1);
    }
}

__device__ __forceinline__ void cp_commit() { asm volatile("cp.async.commit_group;"); }
template<int N> __device__ __forceinline__ void cp_wait() {
    asm volatile("cp.async.wait_group %0;" :: "n"(N));
}
__device__ __forceinline__ void gbar(int g) {   // 64-thread named barrier per group
    asm volatile("bar.sync %0, %1;" :: "r"(g + 1), "r"(GTHREADS) : "memory");
}
__device__ __forceinline__ void ldsm_x4(uint32_t* r, uint32_t addr) {
    asm volatile("ldmatrix.sync.aligned.m8n8.x4.shared.b16 {%0,%1,%2,%3}, [%4];"
                 : "=r"(r[0]), "=r"(r[1]), "=r"(r[2]), "=r"(r[3]) : "r"(addr));
}

// Gather one neighbor slab j: 64 rows x 64B, 4 cp.async(16B) per group thread.
__device__ __forceinline__ void gather_slab(const int* __restrict__ sidx, int j,
                                            uint32_t abuf, int gtid)
{
    #pragma unroll
    for (int i = 0; i < 4; ++i) {
        int o   = i * GTHREADS + gtid;         // 0..255
        int r   = o >> 2;
        int seg = o & 3;
        int idx = sidx[r * FE + j];
        const char* src = (const char*)g_ch + ((size_t)(unsigned)idx << 6) + (seg << 4);
        uint32_t dst = abuf + (uint32_t)r * (ASTRIDE * 4) + (uint32_t)(seg << 4);
        asm volatile("cp.async.cg.shared.global [%0], [%1], 16;" :: "r"(dst), "l"(src));
    }
}

// Stage 64x9 neighbor indices for one tile (tail: per-element clamp).
__device__ __forceinline__ void stage_idx(const int* __restrict__ nbr, int tile,
                                          uint32_t dst, int gtid)
{
    const size_t base = (size_t)tile * (BLOCK_M * FE);
    if (base + BLOCK_M * FE <= (size_t)NFINE * FE) {
        #pragma unroll
        for (int c = gtid; c < BLOCK_M * FE / 4; c += GTHREADS)
            asm volatile("cp.async.ca.shared.global [%0], [%1], 16;"
                         :: "r"(dst + c * 16), "l"(nbr + base + c * 4));
    } else {
        const size_t gmax = (size_t)NFINE * FE - 1;
        for (int i = gtid; i < BLOCK_M * FE; i += GTHREADS) {
            size_t g = base + i; if (g > gmax) g = gmax;
            asm volatile("cp.async.ca.shared.global [%0], [%1], 4;"
                         :: "r"(dst + i * 4), "l"(nbr + g));
        }
    }
}

__global__ void __launch_bounds__(THREADS, 1)
finefy_fp16_kernel(const int*   __restrict__ nbr,
                   const float* __restrict__ weight,
                   float*       __restrict__ out,
                   int numTiles)
{
    extern __shared__ uint32_t sm_[];
    const uint32_t sb = (uint32_t)__cvta_generic_to_shared(sm_);

    const int tid  = threadIdx.x;
    const int grp  = tid >> 6;       // pipeline group 0..7
    const int gtid = tid & 63;
    const int lane = tid & 31;
    const int qr   = lane >> 2;      // 0..7
    const int qc   = lane & 3;       // 0..3
    const int nh   = gtid >> 5;      // n-half (cols nh*32..+31); both warps cover m64

    // Weight -> fp16 n-major: half index = n*(BSTRIDE*2) + k. One-time scatter.
    for (int i = tid; i < 288 * NF; i += THREADS) {
        int k = i >> 6, n = i & 63;
        ((__half*)sm_)[n * (BSTRIDE * 2) + k] = __float2half_rn(weight[i]);
    }
    __syncthreads();   // last CTA-wide barrier; groups run independently after this

    const uint32_t a_base   = sb + A_OFF(grp) * 4;
    const uint32_t idx_base = sb + IDX_OFF(grp) * 4;

    // Per-lane ldmatrix address offsets (bytes).
    const uint32_t a_lane_off = (((lane & 15) * ASTRIDE) + ((lane >> 4) * 4)) * 4;
    const uint32_t b_lane_off = (uint32_t)(nh * 32 + ((lane >> 3) << 3) + (lane & 7))
                                * (BSTRIDE * 4);

    const int step = gridDim.x * NGRP;
    int tile = blockIdx.x * NGRP + grp;
    int ibuf = 0;       // idx buffer holding current tile's indices
    int cons = 0;       // slab buffer about to be consumed (cycles mod 3)

    // ---- Prologue: stage idx, then fill 2 of the 3 slab buffers ----
    if (tile < numTiles) {
        stage_idx(nbr, tile, idx_base, gtid);
        cp_commit(); cp_wait<0>(); gbar(grp);
        const int* sidx0 = (const int*)(sm_ + IDX_OFF(grp));
        #pragma unroll
        for (int p = 0; p < 2; ++p) {
            gather_slab(sidx0, p, a_base + p * (A_U32 * 4), gtid);
            cp_commit();
        }
    }

    for (; tile < numTiles; tile += step) {
        const int* sidx  = (const int*)(sm_ + IDX_OFF(grp) + ibuf * IDX_U32);
        const int* nsidx = (const int*)(sm_ + IDX_OFF(grp) + (ibuf ^ 1) * IDX_U32);
        const bool has_next = (tile + step) < numTiles;

        float acc[4][4][4];   // [m16-quarter][n8-tile][frag]
        #pragma unroll
        for (int i = 0; i < 4; ++i)
            #pragma unroll
            for (int t = 0; t < 4; ++t) {
                acc[i][t][0] = 0.f; acc[i][t][1] = 0.f;
                acc[i][t][2] = 0.f; acc[i][t][3] = 0.f;
            }

        #pragma unroll
        for (int j = 0; j < FE; ++j) {
            cp_wait<1>();      // slab j landed (only slab j+1's group still pending)
            gbar(grp);         // also proves all warps finished slab j-1's buffer

            // ---- Produce slab j+2 into slab j-1's buffer ((cons+2)%3) ----
            uint32_t freed = a_base + ((cons + 2) % NBUF) * (A_U32 * 4);
            if (j + 2 < FE) {
                gather_slab(sidx, j + 2, freed, gtid);
                if (j == 0 && has_next)  // lands by j=2's wait; first used at j=7
                    stage_idx(nbr, tile + step, idx_base + (ibuf ^ 1) * (IDX_U32 * 4), gtid);
            } else if (has_next) {
                gather_slab(nsidx, j - 7, freed, gtid);   // next tile's slabs 0..1
            }
            cp_commit();       // exactly one group per j (possibly empty)

            // ---- Compute slab j from buffer `cons`: warp tile m64 x n32 ----
            const uint32_t a_slab = a_base + cons * (A_U32 * 4) + a_lane_off;
            const uint32_t b_slab = sb + b_lane_off + (uint32_t)j * 64;  // j*32 halves

            #pragma unroll
            for (int kk = 0; kk < 2; ++kk) {     // two k16 steps cover 32 dims
                uint32_t bl[4], bh[4];
                ldsm_x4(bl, b_slab + kk * 32);        // b0 for t=0..3 (k lo 8)
                ldsm_x4(bh, b_slab + kk * 32 + 16);   // b1 for t=0..3 (k hi 8)

                #pragma unroll
                for (int s2 = 0; s2 < 4; ++s2) { // four m16 quarters of m64
                    uint32_t a[4];
                    ldsm_x4(a, a_slab + (uint32_t)(s2 * 16 * ASTRIDE + kk * 8) * 4);

                    #pragma unroll
                    for (int t = 0; t < 4; ++t) {
                        asm volatile(
                            "mma.sync.aligned.m16n8k16.row.col.f32.f16.f16.f32 "
                            "{%0,%1,%2,%3}, {%4,%5,%6,%7}, {%8,%9}, {%0,%1,%2,%3};"
                            : "+f"(acc[s2][t][0]), "+f"(acc[s2][t][1]),
                              "+f"(acc[s2][t][2]), "+f"(acc[s2][t][3])
                            : "r"(a[0]), "r"(a[1]), "r"(a[2]), "r"(a[3]),
                              "r"(bl[t]), "r"(bh[t]));
                    }
                }
            }
            cons = (cons + 1) % NBUF;
        }

        // Epilogue: next tile's slabs 0..1 land underneath these stores.
        const int rowbase = tile * BLOCK_M;
        #pragma unroll
        for (int s2 = 0; s2 < 4; ++s2) {
            #pragma unroll
            for (int h = 0; h < 2; ++h) {
                int r = rowbase + s2 * 16 + h * 8 + qr;
                if (r < NFINE) {
                    float2* po = (float2*)(out + (size_t)r * NF + nh * 32 + qc * 2);
                    #pragma unroll
                    for (int t = 0; t < 4; ++t)
                        __stcs(po + t * 4,
                               make_float2(acc[s2][t][2*h], acc[s2][t][2*h + 1]));
                }
            }
        }
        ibuf ^= 1;
    }
}

extern "C" void kernel_launch(void* const* d_in, const int* in_sizes, int n_in,
                              void* d_out, int out_size)
{
    const float* coarse = (const float*)d_in[0];   // [250000, 32] f32
    const int*   nbr    = (const int*)  d_in[1];   // [1000000, 9] i32
    const float* weight = (const float*)d_in[2];   // [288, 64] f32
    float*       out    = (float*)d_out;           // [1000000, 64] f32

    cudaFuncSetAttribute(finefy_fp16_kernel,
                         cudaFuncAttributeMaxDynamicSharedMemorySize, SMEM_BYTES);

    int nsm = 148;
    cudaDeviceGetAttribute(&nsm, cudaDevAttrMultiProcessorCount, 0);

    // Pre-pass: convert coarse lattice to fp16 (deterministic, graph-capturable).
    conv_coarse<<<nsm * 4, 256>>>((const float4*)coarse);

    const int numTiles = (NFINE + BLOCK_M - 1) / BLOCK_M;   // 15625
    finefy_fp16_kernel<<<nsm, THREADS, SMEM_BYTES>>>(nbr, weight, out, numTiles);
}

// round 16
// speedup vs baseline: 1.5812x; 1.0245x over previous
#include <cuda_runtime.h>
#include <cuda_fp16.h>
#include <cstdint>

#define NFINE   1000000
#define NCOARSE 250000
#define FE      9
#define NF      64
#define BLOCK_M 32               // per warp-pipeline tile
#define THREADS 512              // 16 independent warp pipelines
#define NGRP    16
#define NBUF    3                // slab buffers per warp (produce-ahead 2)
#define BSTRIDE 148              // B n-major row stride (u32 words) == 20 mod 32 ->
                                 // 8-row ldmatrix phases hit disjoint bank quads
#define ASTRIDE 20               // A row stride (u32 words): same conflict-free pattern

// smem layout (u32 units)
#define WS_U32   (NF * BSTRIDE)                // 9472 (W as [n][k] halves, shared)
#define A_U32    (BLOCK_M * ASTRIDE)           // 640 per slab buffer
#define AG_U32   (NBUF * A_U32)                // 1920 per warp
#define A_OFF(g)   (WS_U32 + (g) * AG_U32)
#define IDX_U32  (BLOCK_M * FE)                // 288 per idx buffer
#define IDX_OFF(g) (WS_U32 + NGRP * AG_U32 + (g) * 2 * IDX_U32)
#define SMEM_U32 (WS_U32 + NGRP * AG_U32 + NGRP * 2 * IDX_U32)  // 49408
#define SMEM_BYTES (SMEM_U32 * 4)              // 197632 B -> 1 CTA/SM

// fp16 copy of coarse values (filled by conv_coarse pre-pass each launch)
__device__ __half g_ch[NCOARSE * 32];          // 16 MB

__global__ void __launch_bounds__(256)
conv_coarse(const float4* __restrict__ src)
{
    uint2* dst = (uint2*)g_ch;
    const int n4 = NCOARSE * 8;
    for (int i = blockIdx.x * blockDim.x + threadIdx.x; i < n4;
         i += gridDim.x * blockDim.x) {
        float4 v = src[i];
        __half2 h0 = __floats2half2_rn(v.x, v.y);
        __half2 h1 = __floats2half2_rn(v.z, v.w);
        dst[i] = make_uint2(*(uint32_t*)&h0, *(uint32_t*)&h1);
    }
}

__device__ __forceinline__ void cp_commit() { asm volatile("cp.async.commit_group;"); }
template<int N> __device__ __forceinline__ void cp_wait() {
    asm volatile("cp.async.wait_group %0;" :: "n"(N));
}
__device__ __forceinline__ void ldsm_x4(uint32_t* r, uint32_t addr) {
    asm volatile("ldmatrix.sync.aligned.m8n8.x4.shared.b16 {%0,%1,%2,%3}, [%4];"
                 : "=r"(r[0]), "=r"(r[1]), "=r"(r[2]), "=r"(r[3]) : "r"(addr));
}

// Gather one neighbor slab j: 32 rows x 64B, 4 cp.async(16B) per lane (warp-private).
__device__ __forceinline__ void gather_slab(const int* __restrict__ sidx, int j,
                                            uint32_t abuf, int lane)
{
    #pragma unroll
    for (int i = 0; i < 4; ++i) {
        int o   = i * 32 + lane;               // 0..127
        int r   = o >> 2;
        int seg = o & 3;
        int idx = sidx[r * FE + j];
        const char* src = (const char*)g_ch + ((size_t)(unsigned)idx << 6) + (seg << 4);
        uint32_t dst = abuf + (uint32_t)r * (ASTRIDE * 4) + (uint32_t)(seg << 4);
        asm volatile("cp.async.cg.shared.global [%0], [%1], 16;" :: "r"(dst), "l"(src));
    }
}

// Stage 32x9 neighbor indices for one tile (tail: per-element clamp). Warp-private.
__device__ __forceinline__ void stage_idx(const int* __restrict__ nbr, int tile,
                                          uint32_t dst, int lane)
{
    const size_t base = (size_t)tile * (BLOCK_M * FE);
    if (base + BLOCK_M * FE <= (size_t)NFINE * FE) {
        #pragma unroll
        for (int c = lane; c < BLOCK_M * FE / 4; c += 32)
            asm volatile("cp.async.ca.shared.global [%0], [%1], 16;"
                         :: "r"(dst + c * 16), "l"(nbr + base + c * 4));
    } else {
        const size_t gmax = (size_t)NFINE * FE - 1;
        for (int i = lane; i < BLOCK_M * FE; i += 32) {
            size_t g = base + i; if (g > gmax) g = gmax;
            asm volatile("cp.async.ca.shared.global [%0], [%1], 4;"
                         :: "r"(dst + i * 4), "l"(nbr + g));
        }
    }
}

__global__ void __launch_bounds__(THREADS, 1)
finefy_fp16_kernel(const int*   __restrict__ nbr,
                   const float* __restrict__ weight,
                   float*       __restrict__ out,
                   int numTiles)
{
    extern __shared__ uint32_t sm_[];
    const uint32_t sb = (uint32_t)__cvta_generic_to_shared(sm_);

    const int tid  = threadIdx.x;
    const int grp  = tid >> 5;       // warp pipeline 0..15
    const int lane = tid & 31;
    const int qr   = lane >> 2;      // 0..7
    const int qc   = lane & 3;       // 0..3

    // Weight -> fp16 n-major: half index = n*(BSTRIDE*2) + k. One-time scatter.
    for (int i = tid; i < 288 * NF; i += THREADS) {
        int k = i >> 6, n = i & 63;
        ((__half*)sm_)[n * (BSTRIDE * 2) + k] = __float2half_rn(weight[i]);
    }
    __syncthreads();   // only CTA-wide barrier; warps run independently after this

    const uint32_t a_base   = sb + A_OFF(grp) * 4;
    const uint32_t idx_base = sb + IDX_OFF(grp) * 4;

    // Per-lane ldmatrix address offsets (bytes).
    const uint32_t a_lane_off = (((lane & 15) * ASTRIDE) + ((lane >> 4) * 4)) * 4;
    const uint32_t b_lane_off = (uint32_t)(((lane >> 3) << 3) + (lane & 7))
                                * (BSTRIDE * 4);

    const int step = gridDim.x * NGRP;
    int tile = blockIdx.x * NGRP + grp;
    int ibuf = 0;       // idx buffer holding current tile's indices
    int cons = 0;       // slab buffer about to be consumed (cycles mod 3)

    // ---- Prologue: stage idx, then fill 2 of the 3 slab buffers ----
    if (tile < numTiles) {
        stage_idx(nbr, tile, idx_base, lane);
        cp_commit(); cp_wait<0>(); __syncwarp();
        const int* sidx0 = (const int*)(sm_ + IDX_OFF(grp));
        #pragma unroll
        for (int p = 0; p < 2; ++p) {
            gather_slab(sidx0, p, a_base + p * (A_U32 * 4), lane);
            cp_commit();
        }
    }

    for (; tile < numTiles; tile += step) {
        const int* sidx  = (const int*)(sm_ + IDX_OFF(grp) + ibuf * IDX_U32);
        const int* nsidx = (const int*)(sm_ + IDX_OFF(grp) + (ibuf ^ 1) * IDX_U32);
        const bool has_next = (tile + step) < numTiles;

        float acc[2][8][4];   // [m16-half][n8-tile][frag]
        #pragma unroll
        for (int i = 0; i < 2; ++i)
            #pragma unroll
            for (int t = 0; t < 8; ++t) {
                acc[i][t][0] = 0.f; acc[i][t][1] = 0.f;
                acc[i][t][2] = 0.f; acc[i][t][3] = 0.f;
            }

        #pragma unroll
        for (int j = 0; j < FE; ++j) {
            cp_wait<1>();      // own slab j landed (only slab j+1's group pending)
            __syncwarp();      // cross-lane visibility; all lanes done with j-1 reads

            // ---- Produce slab j+2 into slab j-1's buffer ((cons+2)%3) ----
            uint32_t freed = a_base + ((cons + 2) % NBUF) * (A_U32 * 4);
            if (j + 2 < FE) {
                gather_slab(sidx, j + 2, freed, lane);
                if (j == 0 && has_next)  // lands by j=2's wait; first used at j=7
                    stage_idx(nbr, tile + step, idx_base + (ibuf ^ 1) * (IDX_U32 * 4), lane);
            } else if (has_next) {
                gather_slab(nsidx, j - 7, freed, lane);   // next tile's slabs 0..1
            }
            cp_commit();       // exactly one group per j (possibly empty)

            // ---- Compute slab j from buffer `cons`: warp tile m32 x n64 ----
            const uint32_t a_slab = a_base + cons * (A_U32 * 4) + a_lane_off;
            const uint32_t b_slab = sb + b_lane_off + (uint32_t)j * 64;  // j*32 halves

            #pragma unroll
            for (int kk = 0; kk < 2; ++kk) {     // two k16 steps cover 32 dims
                uint32_t b0l[4], b0h[4], b1l[4], b1h[4];
                ldsm_x4(b0l, b_slab + kk * 32);                       // t=0..3, k lo
                ldsm_x4(b0h, b_slab + kk * 32 + 16);                  // t=0..3, k hi
                ldsm_x4(b1l, b_slab + 32 * (BSTRIDE * 4) + kk * 32);       // t=4..7
                ldsm_x4(b1h, b_slab + 32 * (BSTRIDE * 4) + kk * 32 + 16);

                #pragma unroll
                for (int s2 = 0; s2 < 2; ++s2) { // two m16 halves of m32
                    uint32_t a[4];
                    ldsm_x4(a, a_slab + (uint32_t)(s2 * 16 * ASTRIDE + kk * 8) * 4);

                    #pragma unroll
                    for (int t = 0; t < 8; ++t) {
                        uint32_t bb0 = (t < 4) ? b0l[t] : b1l[t - 4];
                        uint32_t bb1 = (t < 4) ? b0h[t] : b1h[t - 4];
                        asm volatile(
                            "mma.sync.aligned.m16n8k16.row.col.f32.f16.f16.f32 "
                            "{%0,%1,%2,%3}, {%4,%5,%6,%7}, {%8,%9}, {%0,%1,%2,%3};"
                            : "+f"(acc[s2][t][0]), "+f"(acc[s2][t][1]),
                              "+f"(acc[s2][t][2]), "+f"(acc[s2][t][3])
                            : "r"(a[0]), "r"(a[1]), "r"(a[2]), "r"(a[3]),
                              "r"(bb0), "r"(bb1));
                    }
                }
            }
            __syncwarp();      // all lanes done reading buffer `cons` before next produce
            cons = (cons + 1) % NBUF;
        }

        // Epilogue: next tile's slabs 0..1 land underneath these stores.
        const int rowbase = tile * BLOCK_M;
        #pragma unroll
        for (int s2 = 0; s2 < 2; ++s2) {
            #pragma unroll
            for (int h = 0; h < 2; ++h) {
                int r = rowbase + s2 * 16 + h * 8 + qr;
                if (r < NFINE) {
                    float2* po = (float2*)(out + (size_t)r * NF + qc * 2);
                    #pragma unroll
                    for (int t = 0; t < 8; ++t)
                        __stcs(po + t * 4,
                               make_float2(acc[s2][t][2*h], acc[s2][t][2*h + 1]));
                }
            }
        }
        ibuf ^= 1;
    }
}

extern "C" void kernel_launch(void* const* d_in, const int* in_sizes, int n_in,
                              void* d_out, int out_size)
{
    const float* coarse = (const float*)d_in[0];   // [250000, 32] f32
    const int*   nbr    = (const int*)  d_in[1];   // [1000000, 9] i32
    const float* weight = (const float*)d_in[2];   // [288, 64] f32
    float*       out    = (float*)d_out;           // [1000000, 64] f32

    cudaFuncSetAttribute(finefy_fp16_kernel,
                         cudaFuncAttributeMaxDynamicSharedMemorySize, SMEM_BYTES);

    int nsm = 148;
    cudaDeviceGetAttribute(&nsm, cudaDevAttrMultiProcessorCount, 0);

    // Pre-pass: convert coarse lattice to fp16 (deterministic, graph-capturable).
    conv_coarse<<<nsm * 4, 256>>>((const float4*)coarse);

    const int numTiles = (NFINE + BLOCK_M - 1) / BLOCK_M;   // 31250
    finefy_fp16_kernel<<<nsm, THREADS, SMEM_BYTES>>>(nbr, weight, out, numTiles);
}